// round 2
// baseline (speedup 1.0000x reference)
#include <cuda_runtime.h>
#include <math.h>

#define B_   16384
#define H_   512
#define H3_  1536
#define FF_  2048
#define OUT_ 4
#define HOR_ 5

// ---- scratch (device globals; no allocation) ----
// g_big is shared between gh [B,1536] and a1 [B,2048]: never live at the same time.
__device__ float g_big[B_ * FF_];
__device__ float g_h1[B_ * H_];
__device__ float g_h2[B_ * H_];
__device__ float g_hx[B_ * H_];
__device__ float g_xy[B_ * OUT_];

// ============================================================
// Generic tiled SGEMM: C[M,N] = op(A)[M,K] @ W[N,K]^T (+bias)(+relu)
// BM=BN=128, BK=16, 256 threads, 8x8 microtile.
// SPLIT_A: A is concat([A,A2], dim=K) with each half having stride 512.
// Requires M%128==0, N%128==0, K%16==0 (true for all shapes here).
// ============================================================
template<bool SPLIT_A, bool IN_RELU, bool BIAS, bool OUT_RELU>
__global__ void __launch_bounds__(256, 2)
gemm_nt(const float* __restrict__ A, const float* __restrict__ A2, int K,
        const float* __restrict__ W, const float* __restrict__ bias,
        float* __restrict__ C, int N)
{
    __shared__ float As[16][132];
    __shared__ float Ws[16][132];

    const int tid  = threadIdx.x;
    const int bm   = blockIdx.x * 128;
    const int bn   = blockIdx.y * 128;
    const int trow = (tid >> 4) * 8;
    const int tcol = (tid & 15) * 8;

    float acc[8][8];
#pragma unroll
    for (int i = 0; i < 8; i++)
#pragma unroll
        for (int j = 0; j < 8; j++) acc[i][j] = 0.f;

    for (int k0 = 0; k0 < K; k0 += 16) {
        // cooperative tile loads: 512 float4 per operand, 2 per thread
#pragma unroll
        for (int it = 0; it < 2; it++) {
            int lin = tid + it * 256;      // 0..511
            int m   = lin >> 2;            // 0..127
            int k4  = (lin & 3) * 4;       // 0,4,8,12
            int gk  = k0 + k4;

            // W tile
            float4 wv = *reinterpret_cast<const float4*>(&W[(size_t)(bn + m) * K + gk]);
            Ws[k4 + 0][m] = wv.x; Ws[k4 + 1][m] = wv.y;
            Ws[k4 + 2][m] = wv.z; Ws[k4 + 3][m] = wv.w;

            // A tile (optionally split-concat, optionally relu'd)
            const float* src;
            size_t aoff;
            if (SPLIT_A) {
                if (gk < 512) { src = A;  aoff = (size_t)(bm + m) * 512 + gk; }
                else          { src = A2; aoff = (size_t)(bm + m) * 512 + (gk - 512); }
            } else {
                src = A; aoff = (size_t)(bm + m) * K + gk;
            }
            float4 av = *reinterpret_cast<const float4*>(&src[aoff]);
            if (IN_RELU) {
                av.x = fmaxf(av.x, 0.f); av.y = fmaxf(av.y, 0.f);
                av.z = fmaxf(av.z, 0.f); av.w = fmaxf(av.w, 0.f);
            }
            As[k4 + 0][m] = av.x; As[k4 + 1][m] = av.y;
            As[k4 + 2][m] = av.z; As[k4 + 3][m] = av.w;
        }
        __syncthreads();

#pragma unroll
        for (int kk = 0; kk < 16; kk++) {
            float a[8], b[8];
#pragma unroll
            for (int i = 0; i < 4; i++) {
                float4 v = *reinterpret_cast<const float4*>(&As[kk][trow + i * 4]);
                a[i * 4 + 0] = v.x; a[i * 4 + 1] = v.y;
                a[i * 4 + 2] = v.z; a[i * 4 + 3] = v.w;
            }
#pragma unroll
            for (int j = 0; j < 4; j++) {
                float4 v = *reinterpret_cast<const float4*>(&Ws[kk][tcol + j * 4]);
                b[j * 4 + 0] = v.x; b[j * 4 + 1] = v.y;
                b[j * 4 + 2] = v.z; b[j * 4 + 3] = v.w;
            }
#pragma unroll
            for (int i = 0; i < 8; i++)
#pragma unroll
                for (int j = 0; j < 8; j++) acc[i][j] = fmaf(a[i], b[j], acc[i][j]);
        }
        __syncthreads();
    }

    float bv[8];
    if (BIAS) {
#pragma unroll
        for (int j = 0; j < 8; j++) bv[j] = bias[bn + tcol + j];
    }
#pragma unroll
    for (int i = 0; i < 8; i++) {
        float v[8];
#pragma unroll
        for (int j = 0; j < 8; j++) {
            float x = acc[i][j];
            if (BIAS) x += bv[j];
            if (OUT_RELU) x = fmaxf(x, 0.f);
            v[j] = x;
        }
        float* dst = &C[(size_t)(bm + trow + i) * N + bn + tcol];
        reinterpret_cast<float4*>(dst)[0] = make_float4(v[0], v[1], v[2], v[3]);
        reinterpret_cast<float4*>(dst)[1] = make_float4(v[4], v[5], v[6], v[7]);
    }
}

// ============================================================
// GRU gate fusion: given gh = h @ w_hh^T (no bias yet), tiny input x[B,4],
// compute h' = (1-z)*n + z*h  with PyTorch (r,z,n) gate order.
// ============================================================
__device__ __forceinline__ float sigmoidf_(float x) {
    return 1.f / (1.f + expf(-x));
}

__global__ void __launch_bounds__(256)
gate_kernel(const float* __restrict__ gh, const float* __restrict__ x, int xstride,
            const float* __restrict__ h, const float* __restrict__ w_ih,
            const float* __restrict__ b_ih, const float* __restrict__ b_hh,
            float* __restrict__ hout)
{
    int idx = blockIdx.x * blockDim.x + threadIdx.x;   // < B*H
    int b = idx >> 9;
    int j = idx & 511;

    const float* xr = &x[(size_t)b * xstride];
    float x0 = xr[0], x1 = xr[1], x2 = xr[2], x3 = xr[3];

    const float* wr = &w_ih[(size_t)j * 4];
    const float* wz = &w_ih[(size_t)(j + 512) * 4];
    const float* wn = &w_ih[(size_t)(j + 1024) * 4];

    float gir = b_ih[j]        + x0*wr[0] + x1*wr[1] + x2*wr[2] + x3*wr[3];
    float giz = b_ih[j + 512]  + x0*wz[0] + x1*wz[1] + x2*wz[2] + x3*wz[3];
    float gin = b_ih[j + 1024] + x0*wn[0] + x1*wn[1] + x2*wn[2] + x3*wn[3];

    const float* gr = &gh[(size_t)b * 1536];
    float ghr = gr[j]        + b_hh[j];
    float ghz = gr[j + 512]  + b_hh[j + 512];
    float ghn = gr[j + 1024] + b_hh[j + 1024];

    float r = sigmoidf_(gir + ghr);
    float z = sigmoidf_(giz + ghz);
    float n = tanhf(gin + r * ghn);

    hout[idx] = (1.f - z) * n + z * h[idx];
}

// ============================================================
// Final thin GEMM: d_xy = a1[B,2048] @ w2[4,2048]^T + b2 ; xy += d_xy ;
// out[:, step, :] = xy.  One warp per batch row.
// ============================================================
__global__ void __launch_bounds__(256)
final_kernel(const float* __restrict__ a1, const float* __restrict__ w2,
             const float* __restrict__ b2, float* __restrict__ xy,
             float* __restrict__ out, int step)
{
    __shared__ float sw[4][2048];
    int tid = threadIdx.x;
    for (int i = tid; i < 4 * 2048; i += 256)
        sw[i >> 11][i & 2047] = w2[i];
    __syncthreads();

    int warp = tid >> 5, lane = tid & 31;
    int b = blockIdx.x * 8 + warp;
    const float* row = &a1[(size_t)b * 2048];

    float s0 = 0.f, s1 = 0.f, s2 = 0.f, s3 = 0.f;
#pragma unroll 4
    for (int k = lane; k < 2048; k += 32) {
        float v = row[k];
        s0 = fmaf(v, sw[0][k], s0);
        s1 = fmaf(v, sw[1][k], s1);
        s2 = fmaf(v, sw[2][k], s2);
        s3 = fmaf(v, sw[3][k], s3);
    }
#pragma unroll
    for (int o = 16; o > 0; o >>= 1) {
        s0 += __shfl_xor_sync(0xFFFFFFFFu, s0, o);
        s1 += __shfl_xor_sync(0xFFFFFFFFu, s1, o);
        s2 += __shfl_xor_sync(0xFFFFFFFFu, s2, o);
        s3 += __shfl_xor_sync(0xFFFFFFFFu, s3, o);
    }
    if (lane == 0) {
        float* xr = &xy[(size_t)b * 4];
        float v0 = xr[0] + s0 + b2[0];
        float v1 = xr[1] + s1 + b2[1];
        float v2 = xr[2] + s2 + b2[2];
        float v3 = xr[3] + s3 + b2[3];
        xr[0] = v0; xr[1] = v1; xr[2] = v2; xr[3] = v3;
        float* orow = &out[(size_t)b * (HOR_ * OUT_) + step * OUT_];
        orow[0] = v0; orow[1] = v1; orow[2] = v2; orow[3] = v3;
    }
}

__global__ void zero_kernel(float* __restrict__ p, int n) {
    int i = blockIdx.x * blockDim.x + threadIdx.x;
    if (i < n) p[i] = 0.f;
}

// ============================================================
// Launch
// ============================================================
extern "C" void kernel_launch(void* const* d_in, const int* in_sizes, int n_in,
                              void* d_out, int out_size)
{
    const float* pv   = (const float*)d_in[0];   // [B,5,4]
    const float* ptf  = (const float*)d_in[1];   // [B,512]
    const float* w_ih = (const float*)d_in[2];   // [1536,4]
    const float* w_hh = (const float*)d_in[3];   // [1536,512]
    const float* b_ih = (const float*)d_in[4];   // [1536]
    const float* b_hh = (const float*)d_in[5];   // [1536]
    const float* w_fc = (const float*)d_in[6];   // [512,1024]
    const float* b_fc = (const float*)d_in[7];   // [512]
    const float* w1   = (const float*)d_in[8];   // [2048,512]
    const float* b1   = (const float*)d_in[9];   // [2048]
    const float* w2   = (const float*)d_in[10];  // [4,2048]
    const float* b2   = (const float*)d_in[11];  // [4]
    float* out = (float*)d_out;

    float *big, *h1, *h2, *hx, *xy;
    cudaGetSymbolAddress((void**)&big, g_big);
    cudaGetSymbolAddress((void**)&h1, g_h1);
    cudaGetSymbolAddress((void**)&h2, g_h2);
    cudaGetSymbolAddress((void**)&hx, g_hx);
    cudaGetSymbolAddress((void**)&xy, g_xy);
    float* gh = big;   // [B,1536] view
    float* a1 = big;   // [B,2048] view (disjoint lifetime from gh)

    zero_kernel<<<(B_ * OUT_ + 255) / 256, 256>>>(xy, B_ * OUT_);

    const dim3 gridHH(B_ / 128, H3_ / 128);   // (128, 12)
    const dim3 gridFC(B_ / 128, H_  / 128);   // (128, 4)
    const dim3 gridM1(B_ / 128, FF_ / 128);   // (128, 16)
    const int  gateBlocks = (B_ * H_) / 256;  // 32768

    for (int step = 0; step < HOR_; step++) {
        const float* hx_in = (step == 0) ? ptf : hx;

        // cell 1: gh = hx_in @ w_hh^T
        gemm_nt<false, false, false, false><<<gridHH, 256>>>(
            hx_in, nullptr, H_, w_hh, nullptr, gh, H3_);
        gate_kernel<<<gateBlocks, 256>>>(gh, xy, OUT_, hx_in,
                                         w_ih, b_ih, b_hh, h1);

        // cell 2: gh = h1 @ w_hh^T, x = predicted_values[:, step]
        gemm_nt<false, false, false, false><<<gridHH, 256>>>(
            h1, nullptr, H_, w_hh, nullptr, gh, H3_);
        gate_kernel<<<gateBlocks, 256>>>(gh, pv + step * OUT_, HOR_ * OUT_, h1,
                                         w_ih, b_ih, b_hh, h2);

        // hx = concat(h1,h2) @ w_fc^T + b_fc   (concat fused via SPLIT_A)
        gemm_nt<true, false, true, false><<<gridFC, 256>>>(
            h1, h2, 2 * H_, w_fc, b_fc, hx, H_);

        // a1 = relu(relu(hx) @ w1^T + b1)
        gemm_nt<false, true, true, true><<<gridM1, 256>>>(
            hx, nullptr, H_, w1, b1, a1, FF_);

        // xy += a1 @ w2^T + b2 ; out[:, step] = xy
        final_kernel<<<B_ / 8, 256>>>(a1, w2, b2, xy, out, step);
    }
}

// round 4
// speedup vs baseline: 2.6375x; 2.6375x over previous
#include <cuda_runtime.h>
#include <math.h>
#include <stdint.h>

#define B_   16384
#define H_   512
#define H3_  1536
#define FF_  2048
#define OUT_ 4
#define HOR_ 5

// ---- scratch (device globals; no allocation) ----
// g_big shared between gh [B,1536] and a1 [B,2048]: disjoint lifetimes.
__device__ float g_big[B_ * FF_];
__device__ float g_h1[B_ * H_];
__device__ float g_h2[B_ * H_];
__device__ float g_hx[B_ * H_];
__device__ float g_xy[B_ * OUT_];

// ============================================================
// tf32 helpers
// ============================================================
__device__ __forceinline__ uint32_t f2tf32(float f) {
    uint32_t u;
    asm("cvt.rna.tf32.f32 %0, %1;" : "=r"(u) : "f"(f));
    return u;
}

__device__ __forceinline__ void mma_tf32(float c[4], const uint32_t a[4],
                                         const uint32_t b[2]) {
    asm volatile(
        "mma.sync.aligned.m16n8k8.row.col.f32.tf32.tf32.f32 "
        "{%0,%1,%2,%3}, {%4,%5,%6,%7}, {%8,%9}, {%0,%1,%2,%3};"
        : "+f"(c[0]), "+f"(c[1]), "+f"(c[2]), "+f"(c[3])
        : "r"(a[0]), "r"(a[1]), "r"(a[2]), "r"(a[3]),
          "r"(b[0]), "r"(b[1]));
}

// ============================================================
// tf32 tensor-core GEMM: C[M,N] = op(A)[M,K] @ W[N,K]^T (+bias)(+relu)
// BM=BN=128, BK=32, 256 threads (8 warps, 4m x 2n), warp tile 32x64.
// SPLIT_A: A = concat([A,A2], dim=K), each half stride 512.
// Requires M%128==0, N%128==0, K%32==0.
// ============================================================
#define SM_STRIDE 36   // 128-row tiles, 32+4 pad -> conflict-free frag loads

template<bool SPLIT_A, bool IN_RELU, bool BIAS, bool OUT_RELU>
__global__ void __launch_bounds__(256, 2)
gemm_tf32(const float* __restrict__ A, const float* __restrict__ A2, int K,
          const float* __restrict__ W, const float* __restrict__ bias,
          float* __restrict__ C, int N)
{
    __shared__ uint32_t As[128 * SM_STRIDE];
    __shared__ uint32_t Ws[128 * SM_STRIDE];

    const int tid  = threadIdx.x;
    const int warp = tid >> 5;
    const int lane = tid & 31;
    const int gid  = lane >> 2;      // group id 0..7
    const int tig  = lane & 3;       // thread-in-group 0..3
    const int wm   = warp >> 1;      // 0..3
    const int wn   = warp & 1;       // 0..1
    const int bm   = blockIdx.x * 128;
    const int bn   = blockIdx.y * 128;

    float acc[2][8][4];
#pragma unroll
    for (int i = 0; i < 2; i++)
#pragma unroll
        for (int j = 0; j < 8; j++)
#pragma unroll
            for (int r = 0; r < 4; r++) acc[i][j][r] = 0.f;

    for (int k0 = 0; k0 < K; k0 += 32) {
        // ---- load 128x32 tiles of A and W, cvt to tf32, store smem ----
#pragma unroll
        for (int it = 0; it < 4; it++) {
            int lin = tid + it * 256;      // 0..1023
            int row = lin >> 3;            // 0..127
            int c4  = (lin & 7) * 4;       // 0..28
            int gk  = k0 + c4;

            float4 wv = *reinterpret_cast<const float4*>(
                &W[(size_t)(bn + row) * K + gk]);
            uint32_t* wd = &Ws[row * SM_STRIDE + c4];
            wd[0] = f2tf32(wv.x); wd[1] = f2tf32(wv.y);
            wd[2] = f2tf32(wv.z); wd[3] = f2tf32(wv.w);

            const float* src;
            size_t aoff;
            if (SPLIT_A) {
                if (gk < 512) { src = A;  aoff = (size_t)(bm + row) * 512 + gk; }
                else          { src = A2; aoff = (size_t)(bm + row) * 512 + (gk - 512); }
            } else {
                src = A; aoff = (size_t)(bm + row) * K + gk;
            }
            float4 av = *reinterpret_cast<const float4*>(&src[aoff]);
            if (IN_RELU) {
                av.x = fmaxf(av.x, 0.f); av.y = fmaxf(av.y, 0.f);
                av.z = fmaxf(av.z, 0.f); av.w = fmaxf(av.w, 0.f);
            }
            uint32_t* ad = &As[row * SM_STRIDE + c4];
            ad[0] = f2tf32(av.x); ad[1] = f2tf32(av.y);
            ad[2] = f2tf32(av.z); ad[3] = f2tf32(av.w);
        }
        __syncthreads();

        // ---- compute: 4 k-slices of 8 ----
#pragma unroll
        for (int kk = 0; kk < 4; kk++) {
            const int kb = kk * 8;
            uint32_t bfr[8][2];
#pragma unroll
            for (int j = 0; j < 8; j++) {
                int nrow = wn * 64 + j * 8 + gid;
                bfr[j][0] = Ws[nrow * SM_STRIDE + kb + tig];
                bfr[j][1] = Ws[nrow * SM_STRIDE + kb + tig + 4];
            }
            uint32_t afr[2][4];
#pragma unroll
            for (int i = 0; i < 2; i++) {
                int mrow = wm * 32 + i * 16 + gid;
                afr[i][0] = As[mrow * SM_STRIDE + kb + tig];
                afr[i][1] = As[(mrow + 8) * SM_STRIDE + kb + tig];
                afr[i][2] = As[mrow * SM_STRIDE + kb + tig + 4];
                afr[i][3] = As[(mrow + 8) * SM_STRIDE + kb + tig + 4];
            }
#pragma unroll
            for (int i = 0; i < 2; i++)
#pragma unroll
                for (int j = 0; j < 8; j++)
                    mma_tf32(acc[i][j], afr[i], bfr[j]);
        }
        __syncthreads();
    }

    // ---- epilogue ----
#pragma unroll
    for (int i = 0; i < 2; i++) {
        int row0 = bm + wm * 32 + i * 16 + gid;
#pragma unroll
        for (int j = 0; j < 8; j++) {
            int col = bn + wn * 64 + j * 8 + tig * 2;
            float b0 = 0.f, b1 = 0.f;
            if (BIAS) { b0 = bias[col]; b1 = bias[col + 1]; }
            float v0 = acc[i][j][0] + b0;
            float v1 = acc[i][j][1] + b1;
            float v2 = acc[i][j][2] + b0;
            float v3 = acc[i][j][3] + b1;
            if (OUT_RELU) {
                v0 = fmaxf(v0, 0.f); v1 = fmaxf(v1, 0.f);
                v2 = fmaxf(v2, 0.f); v3 = fmaxf(v3, 0.f);
            }
            *reinterpret_cast<float2*>(&C[(size_t)row0 * N + col])
                = make_float2(v0, v1);
            *reinterpret_cast<float2*>(&C[(size_t)(row0 + 8) * N + col])
                = make_float2(v2, v3);
        }
    }
}

// ============================================================
// GRU gate fusion (PyTorch r,z,n order)
// ============================================================
__device__ __forceinline__ float sigmoidf_(float x) {
    return 1.f / (1.f + expf(-x));
}

__global__ void __launch_bounds__(256)
gate_kernel(const float* __restrict__ gh, const float* __restrict__ x, int xstride,
            const float* __restrict__ h, const float* __restrict__ w_ih,
            const float* __restrict__ b_ih, const float* __restrict__ b_hh,
            float* __restrict__ hout)
{
    int idx = blockIdx.x * blockDim.x + threadIdx.x;   // < B*H
    int b = idx >> 9;
    int j = idx & 511;

    const float* xr = &x[(size_t)b * xstride];
    float x0 = xr[0], x1 = xr[1], x2 = xr[2], x3 = xr[3];

    const float* wr = &w_ih[(size_t)j * 4];
    const float* wz = &w_ih[(size_t)(j + 512) * 4];
    const float* wn = &w_ih[(size_t)(j + 1024) * 4];

    float gir = b_ih[j]        + x0*wr[0] + x1*wr[1] + x2*wr[2] + x3*wr[3];
    float giz = b_ih[j + 512]  + x0*wz[0] + x1*wz[1] + x2*wz[2] + x3*wz[3];
    float gin = b_ih[j + 1024] + x0*wn[0] + x1*wn[1] + x2*wn[2] + x3*wn[3];

    const float* gr = &gh[(size_t)b * 1536];
    float ghr = gr[j]        + b_hh[j];
    float ghz = gr[j + 512]  + b_hh[j + 512];
    float ghn = gr[j + 1024] + b_hh[j + 1024];

    float r = sigmoidf_(gir + ghr);
    float z = sigmoidf_(giz + ghz);
    float n = tanhf(gin + r * ghn);

    hout[idx] = (1.f - z) * n + z * h[idx];
}

// ============================================================
// Final thin GEMM: xy += a1 @ w2^T + b2 ; out[:, step] = xy
// ============================================================
__global__ void __launch_bounds__(256)
final_kernel(const float* __restrict__ a1, const float* __restrict__ w2,
             const float* __restrict__ b2, float* __restrict__ xy,
             float* __restrict__ out, int step)
{
    __shared__ float sw[4][2048];
    int tid = threadIdx.x;
    for (int i = tid; i < 4 * 2048; i += 256)
        sw[i >> 11][i & 2047] = w2[i];
    __syncthreads();

    int warp = tid >> 5, lane = tid & 31;
    int b = blockIdx.x * 8 + warp;
    const float* row = &a1[(size_t)b * 2048];

    float s0 = 0.f, s1 = 0.f, s2 = 0.f, s3 = 0.f;
#pragma unroll 4
    for (int k = lane; k < 2048; k += 32) {
        float v = row[k];
        s0 = fmaf(v, sw[0][k], s0);
        s1 = fmaf(v, sw[1][k], s1);
        s2 = fmaf(v, sw[2][k], s2);
        s3 = fmaf(v, sw[3][k], s3);
    }
#pragma unroll
    for (int o = 16; o > 0; o >>= 1) {
        s0 += __shfl_xor_sync(0xFFFFFFFFu, s0, o);
        s1 += __shfl_xor_sync(0xFFFFFFFFu, s1, o);
        s2 += __shfl_xor_sync(0xFFFFFFFFu, s2, o);
        s3 += __shfl_xor_sync(0xFFFFFFFFu, s3, o);
    }
    if (lane == 0) {
        float* xr = &xy[(size_t)b * 4];
        float v0 = xr[0] + s0 + b2[0];
        float v1 = xr[1] + s1 + b2[1];
        float v2 = xr[2] + s2 + b2[2];
        float v3 = xr[3] + s3 + b2[3];
        xr[0] = v0; xr[1] = v1; xr[2] = v2; xr[3] = v3;
        float* orow = &out[(size_t)b * (HOR_ * OUT_) + step * OUT_];
        orow[0] = v0; orow[1] = v1; orow[2] = v2; orow[3] = v3;
    }
}

__global__ void zero_kernel(float* __restrict__ p, int n) {
    int i = blockIdx.x * blockDim.x + threadIdx.x;
    if (i < n) p[i] = 0.f;
}

// ============================================================
// Launch
// ============================================================
extern "C" void kernel_launch(void* const* d_in, const int* in_sizes, int n_in,
                              void* d_out, int out_size)
{
    const float* pv   = (const float*)d_in[0];   // [B,5,4]
    const float* ptf  = (const float*)d_in[1];   // [B,512]
    const float* w_ih = (const float*)d_in[2];   // [1536,4]
    const float* w_hh = (const float*)d_in[3];   // [1536,512]
    const float* b_ih = (const float*)d_in[4];   // [1536]
    const float* b_hh = (const float*)d_in[5];   // [1536]
    const float* w_fc = (const float*)d_in[6];   // [512,1024]
    const float* b_fc = (const float*)d_in[7];   // [512]
    const float* w1   = (const float*)d_in[8];   // [2048,512]
    const float* b1   = (const float*)d_in[9];   // [2048]
    const float* w2   = (const float*)d_in[10];  // [4,2048]
    const float* b2   = (const float*)d_in[11];  // [4]
    float* out = (float*)d_out;

    float *big, *h1, *h2, *hx, *xy;
    cudaGetSymbolAddress((void**)&big, g_big);
    cudaGetSymbolAddress((void**)&h1, g_h1);
    cudaGetSymbolAddress((void**)&h2, g_h2);
    cudaGetSymbolAddress((void**)&hx, g_hx);
    cudaGetSymbolAddress((void**)&xy, g_xy);
    float* gh = big;   // [B,1536] view
    float* a1 = big;   // [B,2048] view (disjoint lifetime)

    zero_kernel<<<(B_ * OUT_ + 255) / 256, 256>>>(xy, B_ * OUT_);

    const dim3 gridHH(B_ / 128, H3_ / 128);   // (128, 12)
    const dim3 gridFC(B_ / 128, H_  / 128);   // (128, 4)
    const dim3 gridM1(B_ / 128, FF_ / 128);   // (128, 16)
    const int  gateBlocks = (B_ * H_) / 256;  // 32768

    for (int step = 0; step < HOR_; step++) {
        const float* hx_in = (step == 0) ? ptf : hx;

        // cell 1: gh = hx_in @ w_hh^T
        gemm_tf32<false, false, false, false><<<gridHH, 256>>>(
            hx_in, nullptr, H_, w_hh, nullptr, gh, H3_);
        gate_kernel<<<gateBlocks, 256>>>(gh, xy, OUT_, hx_in,
                                         w_ih, b_ih, b_hh, h1);

        // cell 2: gh = h1 @ w_hh^T
        gemm_tf32<false, false, false, false><<<gridHH, 256>>>(
            h1, nullptr, H_, w_hh, nullptr, gh, H3_);
        gate_kernel<<<gateBlocks, 256>>>(gh, pv + step * OUT_, HOR_ * OUT_, h1,
                                         w_ih, b_ih, b_hh, h2);

        // hx = concat(h1,h2) @ w_fc^T + b_fc
        gemm_tf32<true, false, true, false><<<gridFC, 256>>>(
            h1, h2, 2 * H_, w_fc, b_fc, hx, H_);

        // a1 = relu(relu(hx) @ w1^T + b1)
        gemm_tf32<false, true, true, true><<<gridM1, 256>>>(
            hx, nullptr, H_, w1, b1, a1, FF_);

        // xy += a1 @ w2^T + b2 ; out[:, step] = xy
        final_kernel<<<B_ / 8, 256>>>(a1, w2, b2, xy, out, step);
    }
}

// round 5
// speedup vs baseline: 2.9192x; 1.1068x over previous
#include <cuda_runtime.h>
#include <math.h>
#include <stdint.h>

#define B_   16384
#define H_   512
#define H3_  1536
#define FF_  2048
#define OUT_ 4
#define HOR_ 5

// ---- scratch (device globals; no allocation) ----
__device__ float g_big[B_ * FF_];     // gh [B,1536] / a1 [B,2048] (disjoint lifetimes)
__device__ float g_h1[B_ * H_];
__device__ float g_hx[B_ * H_];
__device__ float g_xy[B_ * OUT_];
// tf32-pre-rounded copies (GEMM A/W operands)
__device__ float g_h1r[B_ * H_];
__device__ float g_h2r[B_ * H_];
__device__ float g_hxr[B_ * H_];
__device__ float g_ptfr[B_ * H_];
__device__ float g_whhr[H3_ * H_];
__device__ float g_wfcr[H_ * 2 * H_];
__device__ float g_w1r[FF_ * H_];

// ============================================================
// tf32 helpers
// ============================================================
__device__ __forceinline__ uint32_t f2tf32(float f) {
    uint32_t u;
    asm("cvt.rna.tf32.f32 %0, %1;" : "=r"(u) : "f"(f));
    return u;
}

__device__ __forceinline__ void mma_tf32(float c[4], const uint32_t a[4],
                                         const uint32_t b[2]) {
    asm volatile(
        "mma.sync.aligned.m16n8k8.row.col.f32.tf32.tf32.f32 "
        "{%0,%1,%2,%3}, {%4,%5,%6,%7}, {%8,%9}, {%0,%1,%2,%3};"
        : "+f"(c[0]), "+f"(c[1]), "+f"(c[2]), "+f"(c[3])
        : "r"(a[0]), "r"(a[1]), "r"(a[2]), "r"(a[3]),
          "r"(b[0]), "r"(b[1]));
}

__device__ __forceinline__ void cp16(uint32_t smem_dst, const float* gsrc) {
    asm volatile("cp.async.cg.shared.global [%0], [%1], 16;"
                 :: "r"(smem_dst), "l"(gsrc));
}

// ============================================================
// Round-to-tf32 copy (prep kernels, vectorized)
// ============================================================
__global__ void round_kernel(const float* __restrict__ src,
                             float* __restrict__ dst, int n4) {
    int i = blockIdx.x * blockDim.x + threadIdx.x;
    if (i < n4) {
        float4 v = reinterpret_cast<const float4*>(src)[i];
        v.x = __uint_as_float(f2tf32(v.x));
        v.y = __uint_as_float(f2tf32(v.y));
        v.z = __uint_as_float(f2tf32(v.z));
        v.w = __uint_as_float(f2tf32(v.w));
        reinterpret_cast<float4*>(dst)[i] = v;
    }
}

__global__ void zero_kernel(float* __restrict__ p, int n) {
    int i = blockIdx.x * blockDim.x + threadIdx.x;
    if (i < n) p[i] = 0.f;
}

// ============================================================
// tf32 tensor-core GEMM with 2-stage cp.async pipeline.
// C[M,N] = A[M,K] @ W[N,K]^T (+bias)(+relu); A,W pre-rounded to tf32 bits.
// BM=BN=128, BK=32, 256 threads (8 warps, 4m x 2n), warp tile 32x64.
// SPLIT_A: A = concat([A,A2], dim=K), each half stride 512 (K%32==0 so
// each BK-tile is entirely within one half).
// DUAL: additionally write Cr = round_tf32(C+bias...) for downstream GEMMs.
// ============================================================
#define SMS 36                     // 32 + 4 pad (floats); row pitch 144B (16B-mult)
#define TILE_ELEMS (128 * SMS)

template<bool SPLIT_A, bool IN_RELU, bool BIAS, bool OUT_RELU, bool DUAL>
__global__ void __launch_bounds__(256, 2)
gemm_tc(const float* __restrict__ A, const float* __restrict__ A2, int K,
        const float* __restrict__ W, const float* __restrict__ bias,
        float* __restrict__ C, float* __restrict__ Cr, int N)
{
    extern __shared__ uint32_t sm[];
    uint32_t* sA = sm;                      // 2 stages x TILE_ELEMS
    uint32_t* sW = sm + 2 * TILE_ELEMS;     // 2 stages x TILE_ELEMS

    const int tid  = threadIdx.x;
    const int warp = tid >> 5;
    const int lane = tid & 31;
    const int gid  = lane >> 2;
    const int tig  = lane & 3;
    const int wm   = warp >> 1;
    const int wn   = warp & 1;
    const int bm   = blockIdx.x * 128;
    const int bn   = blockIdx.y * 128;

    float acc[2][8][4];
#pragma unroll
    for (int i = 0; i < 2; i++)
#pragma unroll
        for (int j = 0; j < 8; j++)
#pragma unroll
            for (int r = 0; r < 4; r++) acc[i][j][r] = 0.f;

    auto issue_tile = [&](int s, int k0) {
#pragma unroll
        for (int it = 0; it < 4; it++) {
            int lin = tid + it * 256;      // 0..1023
            int row = lin >> 3;            // 0..127
            int c4  = (lin & 7) * 4;       // 0..28

            const float* wsrc = &W[(size_t)(bn + row) * K + k0 + c4];
            cp16(__cvta_generic_to_shared(&sW[s * TILE_ELEMS + row * SMS + c4]), wsrc);

            const float* asrc;
            if (SPLIT_A) {
                if (k0 < 512) asrc = &A [(size_t)(bm + row) * 512 + k0 + c4];
                else          asrc = &A2[(size_t)(bm + row) * 512 + (k0 - 512) + c4];
            } else {
                asrc = &A[(size_t)(bm + row) * K + k0 + c4];
            }
            cp16(__cvta_generic_to_shared(&sA[s * TILE_ELEMS + row * SMS + c4]), asrc);
        }
        asm volatile("cp.async.commit_group;");
    };

    const int T = K >> 5;
    issue_tile(0, 0);

    for (int t = 0; t < T; t++) {
        if (t + 1 < T) {
            issue_tile((t + 1) & 1, (t + 1) * 32);
            asm volatile("cp.async.wait_group 1;");
        } else {
            asm volatile("cp.async.wait_group 0;");
        }
        __syncthreads();

        const uint32_t* As = &sA[(t & 1) * TILE_ELEMS];
        const uint32_t* Ws = &sW[(t & 1) * TILE_ELEMS];

#pragma unroll
        for (int kk = 0; kk < 4; kk++) {
            const int kb = kk * 8;
            uint32_t bfr[8][2];
#pragma unroll
            for (int j = 0; j < 8; j++) {
                int nrow = wn * 64 + j * 8 + gid;
                bfr[j][0] = Ws[nrow * SMS + kb + tig];
                bfr[j][1] = Ws[nrow * SMS + kb + tig + 4];
            }
            uint32_t afr[2][4];
#pragma unroll
            for (int i = 0; i < 2; i++) {
                int mrow = wm * 32 + i * 16 + gid;
                afr[i][0] = As[mrow * SMS + kb + tig];
                afr[i][1] = As[(mrow + 8) * SMS + kb + tig];
                afr[i][2] = As[mrow * SMS + kb + tig + 4];
                afr[i][3] = As[(mrow + 8) * SMS + kb + tig + 4];
                if (IN_RELU) {
#pragma unroll
                    for (int r = 0; r < 4; r++) {
                        float f = fmaxf(__uint_as_float(afr[i][r]), 0.f);
                        afr[i][r] = __float_as_uint(f);
                    }
                }
            }
#pragma unroll
            for (int i = 0; i < 2; i++)
#pragma unroll
                for (int j = 0; j < 8; j++)
                    mma_tf32(acc[i][j], afr[i], bfr[j]);
        }
        __syncthreads();
    }

    // ---- epilogue ----
#pragma unroll
    for (int i = 0; i < 2; i++) {
        int row0 = bm + wm * 32 + i * 16 + gid;
#pragma unroll
        for (int j = 0; j < 8; j++) {
            int col = bn + wn * 64 + j * 8 + tig * 2;
            float b0 = 0.f, b1 = 0.f;
            if (BIAS) { b0 = bias[col]; b1 = bias[col + 1]; }
            float v0 = acc[i][j][0] + b0;
            float v1 = acc[i][j][1] + b1;
            float v2 = acc[i][j][2] + b0;
            float v3 = acc[i][j][3] + b1;
            if (OUT_RELU) {
                v0 = fmaxf(v0, 0.f); v1 = fmaxf(v1, 0.f);
                v2 = fmaxf(v2, 0.f); v3 = fmaxf(v3, 0.f);
            }
            *reinterpret_cast<float2*>(&C[(size_t)row0 * N + col])
                = make_float2(v0, v1);
            *reinterpret_cast<float2*>(&C[(size_t)(row0 + 8) * N + col])
                = make_float2(v2, v3);
            if (DUAL) {
                *reinterpret_cast<float2*>(&Cr[(size_t)row0 * N + col])
                    = make_float2(__uint_as_float(f2tf32(v0)),
                                  __uint_as_float(f2tf32(v1)));
                *reinterpret_cast<float2*>(&Cr[(size_t)(row0 + 8) * N + col])
                    = make_float2(__uint_as_float(f2tf32(v2)),
                                  __uint_as_float(f2tf32(v3)));
            }
        }
    }
}

// ============================================================
// GRU gate fusion (PyTorch r,z,n order). Dual output:
// hout fp32 (elementwise h path), houtr tf32-rounded (GEMM A operand).
// ============================================================
__device__ __forceinline__ float sigmoidf_(float x) {
    return 1.f / (1.f + expf(-x));
}

__global__ void __launch_bounds__(256)
gate_kernel(const float* __restrict__ gh, const float* __restrict__ x, int xstride,
            const float* __restrict__ h, const float* __restrict__ w_ih,
            const float* __restrict__ b_ih, const float* __restrict__ b_hh,
            float* __restrict__ hout, float* __restrict__ houtr)
{
    int idx = blockIdx.x * blockDim.x + threadIdx.x;   // < B*H
    int b = idx >> 9;
    int j = idx & 511;

    const float* xr = &x[(size_t)b * xstride];
    float x0 = xr[0], x1 = xr[1], x2 = xr[2], x3 = xr[3];

    const float* wr = &w_ih[(size_t)j * 4];
    const float* wz = &w_ih[(size_t)(j + 512) * 4];
    const float* wn = &w_ih[(size_t)(j + 1024) * 4];

    float gir = b_ih[j]        + x0*wr[0] + x1*wr[1] + x2*wr[2] + x3*wr[3];
    float giz = b_ih[j + 512]  + x0*wz[0] + x1*wz[1] + x2*wz[2] + x3*wz[3];
    float gin = b_ih[j + 1024] + x0*wn[0] + x1*wn[1] + x2*wn[2] + x3*wn[3];

    const float* gr = &gh[(size_t)b * 1536];
    float ghr = gr[j]        + b_hh[j];
    float ghz = gr[j + 512]  + b_hh[j + 512];
    float ghn = gr[j + 1024] + b_hh[j + 1024];

    float r = sigmoidf_(gir + ghr);
    float z = sigmoidf_(giz + ghz);
    float n = tanhf(gin + r * ghn);

    float hv = (1.f - z) * n + z * h[idx];
    if (hout) hout[idx] = hv;
    houtr[idx] = __uint_as_float(f2tf32(hv));
}

// ============================================================
// Final thin GEMM: xy += a1 @ w2^T + b2 ; out[:, step] = xy
// ============================================================
__global__ void __launch_bounds__(256)
final_kernel(const float* __restrict__ a1, const float* __restrict__ w2,
             const float* __restrict__ b2, float* __restrict__ xy,
             float* __restrict__ out, int step)
{
    __shared__ float sw[4][2048];
    int tid = threadIdx.x;
    for (int i = tid; i < 4 * 2048; i += 256)
        sw[i >> 11][i & 2047] = w2[i];
    __syncthreads();

    int warp = tid >> 5, lane = tid & 31;
    int b = blockIdx.x * 8 + warp;
    const float* row = &a1[(size_t)b * 2048];

    float s0 = 0.f, s1 = 0.f, s2 = 0.f, s3 = 0.f;
#pragma unroll 4
    for (int k = lane; k < 2048; k += 32) {
        float v = row[k];
        s0 = fmaf(v, sw[0][k], s0);
        s1 = fmaf(v, sw[1][k], s1);
        s2 = fmaf(v, sw[2][k], s2);
        s3 = fmaf(v, sw[3][k], s3);
    }
#pragma unroll
    for (int o = 16; o > 0; o >>= 1) {
        s0 += __shfl_xor_sync(0xFFFFFFFFu, s0, o);
        s1 += __shfl_xor_sync(0xFFFFFFFFu, s1, o);
        s2 += __shfl_xor_sync(0xFFFFFFFFu, s2, o);
        s3 += __shfl_xor_sync(0xFFFFFFFFu, s3, o);
    }
    if (lane == 0) {
        float* xr = &xy[(size_t)b * 4];
        float v0 = xr[0] + s0 + b2[0];
        float v1 = xr[1] + s1 + b2[1];
        float v2 = xr[2] + s2 + b2[2];
        float v3 = xr[3] + s3 + b2[3];
        xr[0] = v0; xr[1] = v1; xr[2] = v2; xr[3] = v3;
        float* orow = &out[(size_t)b * (HOR_ * OUT_) + step * OUT_];
        orow[0] = v0; orow[1] = v1; orow[2] = v2; orow[3] = v3;
    }
}

// ============================================================
// Launch
// ============================================================
#define SMEM_BYTES (4u * TILE_ELEMS * sizeof(uint32_t))

extern "C" void kernel_launch(void* const* d_in, const int* in_sizes, int n_in,
                              void* d_out, int out_size)
{
    const float* pv   = (const float*)d_in[0];
    const float* ptf  = (const float*)d_in[1];
    const float* w_ih = (const float*)d_in[2];
    const float* w_hh = (const float*)d_in[3];
    const float* b_ih = (const float*)d_in[4];
    const float* b_hh = (const float*)d_in[5];
    const float* w_fc = (const float*)d_in[6];
    const float* b_fc = (const float*)d_in[7];
    const float* w1   = (const float*)d_in[8];
    const float* b1   = (const float*)d_in[9];
    const float* w2   = (const float*)d_in[10];
    const float* b2   = (const float*)d_in[11];
    float* out = (float*)d_out;

    float *big, *h1, *hx, *xy, *h1r, *h2r, *hxr, *ptfr, *whhr, *wfcr, *w1r;
    cudaGetSymbolAddress((void**)&big,  g_big);
    cudaGetSymbolAddress((void**)&h1,   g_h1);
    cudaGetSymbolAddress((void**)&hx,   g_hx);
    cudaGetSymbolAddress((void**)&xy,   g_xy);
    cudaGetSymbolAddress((void**)&h1r,  g_h1r);
    cudaGetSymbolAddress((void**)&h2r,  g_h2r);
    cudaGetSymbolAddress((void**)&hxr,  g_hxr);
    cudaGetSymbolAddress((void**)&ptfr, g_ptfr);
    cudaGetSymbolAddress((void**)&whhr, g_whhr);
    cudaGetSymbolAddress((void**)&wfcr, g_wfcr);
    cudaGetSymbolAddress((void**)&w1r,  g_w1r);
    float* gh = big;
    float* a1 = big;

    // opt-in dynamic smem for all GEMM instantiations
    cudaFuncSetAttribute(gemm_tc<false,false,false,false,false>,
        cudaFuncAttributeMaxDynamicSharedMemorySize, SMEM_BYTES);
    cudaFuncSetAttribute(gemm_tc<true,false,true,false,true>,
        cudaFuncAttributeMaxDynamicSharedMemorySize, SMEM_BYTES);
    cudaFuncSetAttribute(gemm_tc<false,true,true,true,false>,
        cudaFuncAttributeMaxDynamicSharedMemorySize, SMEM_BYTES);

    // ---- prep: round weights + ptf to tf32 bits; zero xy ----
    round_kernel<<<(H3_ * H_ / 4 + 255) / 256, 256>>>(w_hh, whhr, H3_ * H_ / 4);
    round_kernel<<<(H_ * 2 * H_ / 4 + 255) / 256, 256>>>(w_fc, wfcr, H_ * 2 * H_ / 4);
    round_kernel<<<(FF_ * H_ / 4 + 255) / 256, 256>>>(w1, w1r, FF_ * H_ / 4);
    round_kernel<<<(B_ * H_ / 4 + 255) / 256, 256>>>(ptf, ptfr, B_ * H_ / 4);
    zero_kernel<<<(B_ * OUT_ + 255) / 256, 256>>>(xy, B_ * OUT_);

    const dim3 gridHH(B_ / 128, H3_ / 128);
    const dim3 gridFC(B_ / 128, H_  / 128);
    const dim3 gridM1(B_ / 128, FF_ / 128);
    const int  gateBlocks = (B_ * H_) / 256;

    for (int step = 0; step < HOR_; step++) {
        const float* hxin_r  = (step == 0) ? ptfr : hxr;  // rounded A operand
        const float* hxin_f  = (step == 0) ? ptf  : hx;   // fp32 h for gate

        // cell 1: gh = hxin_r @ whhr^T
        gemm_tc<false, false, false, false, false><<<gridHH, 256, SMEM_BYTES>>>(
            hxin_r, nullptr, H_, whhr, nullptr, gh, nullptr, H3_);
        gate_kernel<<<gateBlocks, 256>>>(gh, xy, OUT_, hxin_f,
                                         w_ih, b_ih, b_hh, h1, h1r);

        // cell 2: gh = h1r @ whhr^T  (h2 only needed as rounded GEMM operand)
        gemm_tc<false, false, false, false, false><<<gridHH, 256, SMEM_BYTES>>>(
            h1r, nullptr, H_, whhr, nullptr, gh, nullptr, H3_);
        gate_kernel<<<gateBlocks, 256>>>(gh, pv + step * OUT_, HOR_ * OUT_, h1,
                                         w_ih, b_ih, b_hh, nullptr, h2r);

        // hx = concat(h1,h2) @ w_fc^T + b_fc   (dual: fp32 hx + rounded hxr)
        gemm_tc<true, false, true, false, true><<<gridFC, 256, SMEM_BYTES>>>(
            h1r, h2r, 2 * H_, wfcr, b_fc, hx, hxr, H_);

        // a1 = relu(relu(hxr) @ w1r^T + b1)
        gemm_tc<false, true, true, true, false><<<gridM1, 256, SMEM_BYTES>>>(
            hxr, nullptr, H_, w1r, b1, a1, nullptr, FF_);

        // xy += a1 @ w2^T + b2 ; out[:, step] = xy
        final_kernel<<<B_ / 8, 256>>>(a1, w2, b2, xy, out, step);
    }
}

// round 8
// speedup vs baseline: 3.1014x; 1.0624x over previous
#include <cuda_runtime.h>
#include <math.h>
#include <stdint.h>

#define B_   16384
#define H_   512
#define FF_  2048
#define OUT_ 4
#define HOR_ 5

// ---- scratch (device globals; no allocation) ----
__device__ float g_h1[B_ * H_];      // cell-1 hidden, fp32 (gate h-term of cell 2)
__device__ float g_hx[B_ * H_];      // fc output fp32 (gate h-term of next step)
__device__ float g_xy[B_ * OUT_];
__device__ float g_dxy[B_ * OUT_];   // MLP partial-sum accumulator
// tf32-pre-rounded copies (GEMM operands)
__device__ float g_h1r[B_ * H_];
__device__ float g_h2r[B_ * H_];
__device__ float g_hxr[B_ * H_];
__device__ float g_ptfr[B_ * H_];
__device__ float g_whhr[3 * H_ * H_];
__device__ float g_wfcr[H_ * 2 * H_];
__device__ float g_w1r[FF_ * H_];

// ============================================================
// helpers
// ============================================================
__device__ __forceinline__ uint32_t f2tf32(float f) {
    uint32_t u;
    asm("cvt.rna.tf32.f32 %0, %1;" : "=r"(u) : "f"(f));
    return u;
}
__device__ __forceinline__ float roundf_tf32(float f) {
    return __uint_as_float(f2tf32(f));
}

__device__ __forceinline__ void mma_tf32(float c[4], const uint32_t a[4],
                                         const uint32_t b[2]) {
    asm volatile(
        "mma.sync.aligned.m16n8k8.row.col.f32.tf32.tf32.f32 "
        "{%0,%1,%2,%3}, {%4,%5,%6,%7}, {%8,%9}, {%0,%1,%2,%3};"
        : "+f"(c[0]), "+f"(c[1]), "+f"(c[2]), "+f"(c[3])
        : "r"(a[0]), "r"(a[1]), "r"(a[2]), "r"(a[3]),
          "r"(b[0]), "r"(b[1]));
}

__device__ __forceinline__ void cp16(void* smem_ptr, const float* gsrc) {
    uint32_t a = (uint32_t)__cvta_generic_to_shared(smem_ptr);
    asm volatile("cp.async.cg.shared.global [%0], [%1], 16;"
                 :: "r"(a), "l"(gsrc));
}

__device__ __forceinline__ float sigmoidf_(float x) {
    return 1.f / (1.f + expf(-x));
}

// ============================================================
// prep kernels
// ============================================================
__global__ void round_kernel(const float* __restrict__ src,
                             float* __restrict__ dst, int n4) {
    int i = blockIdx.x * blockDim.x + threadIdx.x;
    if (i < n4) {
        float4 v = reinterpret_cast<const float4*>(src)[i];
        v.x = roundf_tf32(v.x); v.y = roundf_tf32(v.y);
        v.z = roundf_tf32(v.z); v.w = roundf_tf32(v.w);
        reinterpret_cast<float4*>(dst)[i] = v;
    }
}

__global__ void zero_kernel(float* __restrict__ p, int n) {
    int i = blockIdx.x * blockDim.x + threadIdx.x;
    if (i < n) p[i] = 0.f;
}

#define SMS 36   // smem row pitch in floats: 32 + 4 pad

// ============================================================
// Gate-fused HH GEMM.
// grid (B/128, 512/64).  CTA computes gh_r/gh_z/gh_n accumulators for
// [128 batch x 64 gate-cols]: A[128,512] vs 3 W-tiles (rows bn+j, +512, +1024).
// Epilogue applies the full GRU cell and writes h' (fp32 opt + tf32-rounded).
// 256 threads (8 warps 4m x 2n), warp tile 32x32 per gate, 2-stage cp.async.
// ============================================================
#define HH_STAGE_ELEMS (320 * SMS)            // A 128 rows + W 192 rows
#define HH_SMEM_BYTES (2u * HH_STAGE_ELEMS * 4u)

__global__ void __launch_bounds__(256)
hh_fused(const float* __restrict__ Ar, const float* __restrict__ Whh,
         const float* __restrict__ hf, const float* __restrict__ x, int xstride,
         const float* __restrict__ w_ih, const float* __restrict__ b_ih,
         const float* __restrict__ b_hh,
         float* __restrict__ hout, float* __restrict__ houtr)
{
    extern __shared__ uint32_t sm[];

    const int tid  = threadIdx.x;
    const int warp = tid >> 5;
    const int lane = tid & 31;
    const int gid  = lane >> 2;
    const int tig  = lane & 3;
    const int wm   = warp >> 1;          // 0..3
    const int wn   = warp & 1;           // 0..1
    const int bm   = blockIdx.x * 128;
    const int bn   = blockIdx.y * 64;

    float acc[3][2][4][4];
#pragma unroll
    for (int g = 0; g < 3; g++)
#pragma unroll
        for (int i = 0; i < 2; i++)
#pragma unroll
            for (int j = 0; j < 4; j++)
#pragma unroll
                for (int r = 0; r < 4; r++) acc[g][i][j][r] = 0.f;

    auto issue = [&](int t) {
        const int s  = t & 1;
        const int k0 = t * 32;
        uint32_t* base = sm + s * HH_STAGE_ELEMS;
#pragma unroll
        for (int it = 0; it < 4; it++) {           // A: 128 rows x 8 chunks
            int lin = tid + it * 256;
            int row = lin >> 3, j = lin & 7;
            cp16(&base[row * SMS + j * 4],
                 &Ar[(size_t)(bm + row) * 512 + k0 + j * 4]);
        }
#pragma unroll
        for (int it = 0; it < 6; it++) {           // W: 192 rows x 8 chunks
            int lin = tid + it * 256;
            int row = lin >> 3, j = lin & 7;
            int g = row >> 6, lr = row & 63;
            cp16(&base[(128 + row) * SMS + j * 4],
                 &Whh[(size_t)(g * 512 + bn + lr) * 512 + k0 + j * 4]);
        }
        asm volatile("cp.async.commit_group;" ::: "memory");
    };

    issue(0);
    for (int t = 0; t < 16; t++) {
        if (t + 1 < 16) {
            issue(t + 1);
            asm volatile("cp.async.wait_group 1;" ::: "memory");
        } else {
            asm volatile("cp.async.wait_group 0;" ::: "memory");
        }
        __syncthreads();

        const uint32_t* sa = sm + (t & 1) * HH_STAGE_ELEMS;
        const uint32_t* sw = sa + 128 * SMS;

#pragma unroll
        for (int kk = 0; kk < 4; kk++) {
            const int kb = kk * 8;
            uint32_t afr[2][4];
#pragma unroll
            for (int i = 0; i < 2; i++) {
                int mrow = wm * 32 + i * 16 + gid;
                afr[i][0] = sa[mrow * SMS + kb + tig];
                afr[i][1] = sa[(mrow + 8) * SMS + kb + tig];
                afr[i][2] = sa[mrow * SMS + kb + tig + 4];
                afr[i][3] = sa[(mrow + 8) * SMS + kb + tig + 4];
            }
            uint32_t bfr[3][4][2];
#pragma unroll
            for (int g = 0; g < 3; g++)
#pragma unroll
                for (int j = 0; j < 4; j++) {
                    int nrow = g * 64 + wn * 32 + j * 8 + gid;
                    bfr[g][j][0] = sw[nrow * SMS + kb + tig];
                    bfr[g][j][1] = sw[nrow * SMS + kb + tig + 4];
                }
#pragma unroll
            for (int g = 0; g < 3; g++)
#pragma unroll
                for (int i = 0; i < 2; i++)
#pragma unroll
                    for (int j = 0; j < 4; j++)
                        mma_tf32(acc[g][i][j], afr[i], bfr[g][j]);
        }
        __syncthreads();
    }

    // ---- fused gate epilogue ----
#pragma unroll
    for (int i = 0; i < 2; i++) {
        const int r0 = bm + wm * 32 + i * 16 + gid;
        const int r1 = r0 + 8;
        const float4 xv0 = *reinterpret_cast<const float4*>(&x[(size_t)r0 * xstride]);
        const float4 xv1 = *reinterpret_cast<const float4*>(&x[(size_t)r1 * xstride]);
#pragma unroll
        for (int j = 0; j < 4; j++) {
            const int col = bn + wn * 32 + j * 8 + tig * 2;
            const float2 hp0 = *reinterpret_cast<const float2*>(&hf[(size_t)r0 * 512 + col]);
            const float2 hp1 = *reinterpret_cast<const float2*>(&hf[(size_t)r1 * 512 + col]);
            float res[2][2];
#pragma unroll
            for (int c = 0; c < 2; c++) {
                const int cc = col + c;
                const float4 wr = *reinterpret_cast<const float4*>(&w_ih[(size_t)cc * 4]);
                const float4 wz = *reinterpret_cast<const float4*>(&w_ih[(size_t)(cc + 512) * 4]);
                const float4 wnn = *reinterpret_cast<const float4*>(&w_ih[(size_t)(cc + 1024) * 4]);
                const float bir = b_ih[cc], biz = b_ih[cc + 512], bin = b_ih[cc + 1024];
                const float bhr = b_hh[cc], bhz = b_hh[cc + 512], bhn = b_hh[cc + 1024];
#pragma unroll
                for (int rr = 0; rr < 2; rr++) {
                    const float4 xv = rr ? xv1 : xv0;
                    float gir = bir + xv.x*wr.x + xv.y*wr.y + xv.z*wr.z + xv.w*wr.w;
                    float giz = biz + xv.x*wz.x + xv.y*wz.y + xv.z*wz.z + xv.w*wz.w;
                    float gin = bin + xv.x*wnn.x + xv.y*wnn.y + xv.z*wnn.z + xv.w*wnn.w;
                    float ghr = acc[0][i][j][rr * 2 + c] + bhr;
                    float ghz = acc[1][i][j][rr * 2 + c] + bhz;
                    float ghn = acc[2][i][j][rr * 2 + c] + bhn;
                    float rg = sigmoidf_(gir + ghr);
                    float zg = sigmoidf_(giz + ghz);
                    float ng = tanhf(gin + rg * ghn);
                    float hprev = rr ? (c ? hp1.y : hp1.x) : (c ? hp0.y : hp0.x);
                    res[rr][c] = (1.f - zg) * ng + zg * hprev;
                }
            }
            if (hout) {
                *reinterpret_cast<float2*>(&hout[(size_t)r0 * 512 + col])
                    = make_float2(res[0][0], res[0][1]);
                *reinterpret_cast<float2*>(&hout[(size_t)r1 * 512 + col])
                    = make_float2(res[1][0], res[1][1]);
            }
            *reinterpret_cast<float2*>(&houtr[(size_t)r0 * 512 + col])
                = make_float2(roundf_tf32(res[0][0]), roundf_tf32(res[0][1]));
            *reinterpret_cast<float2*>(&houtr[(size_t)r1 * 512 + col])
                = make_float2(roundf_tf32(res[1][0]), roundf_tf32(res[1][1]));
        }
    }
}

// ============================================================
// fc GEMM (R5-proven core): hx = concat(h1r,h2r) @ wfcr^T + b_fc
// DUAL write: hx fp32 + hxr rounded.  BM=BN=128, BK=32, 2-stage cp.async.
// ============================================================
#define TILE_ELEMS (128 * SMS)
#define GC_SMEM_BYTES (4u * TILE_ELEMS * 4u)

__global__ void __launch_bounds__(256, 2)
gemm_fc(const float* __restrict__ A, const float* __restrict__ A2,
        const float* __restrict__ W, const float* __restrict__ bias,
        float* __restrict__ C, float* __restrict__ Cr)
{
    extern __shared__ uint32_t sm[];
    uint32_t* sA = sm;
    uint32_t* sW = sm + 2 * TILE_ELEMS;
    const int K = 1024, N = 512;

    const int tid  = threadIdx.x;
    const int warp = tid >> 5;
    const int lane = tid & 31;
    const int gid  = lane >> 2;
    const int tig  = lane & 3;
    const int wm   = warp >> 1;
    const int wn   = warp & 1;
    const int bm   = blockIdx.x * 128;
    const int bn   = blockIdx.y * 128;

    float acc[2][8][4];
#pragma unroll
    for (int i = 0; i < 2; i++)
#pragma unroll
        for (int j = 0; j < 8; j++)
#pragma unroll
            for (int r = 0; r < 4; r++) acc[i][j][r] = 0.f;

    auto issue_tile = [&](int s, int k0) {
#pragma unroll
        for (int it = 0; it < 4; it++) {
            int lin = tid + it * 256;
            int row = lin >> 3;
            int c4  = (lin & 7) * 4;
            cp16(&sW[s * TILE_ELEMS + row * SMS + c4],
                 &W[(size_t)(bn + row) * K + k0 + c4]);
            const float* asrc = (k0 < 512)
                ? &A [(size_t)(bm + row) * 512 + k0 + c4]
                : &A2[(size_t)(bm + row) * 512 + (k0 - 512) + c4];
            cp16(&sA[s * TILE_ELEMS + row * SMS + c4], asrc);
        }
        asm volatile("cp.async.commit_group;" ::: "memory");
    };

    const int T = K >> 5;
    issue_tile(0, 0);

    for (int t = 0; t < T; t++) {
        if (t + 1 < T) {
            issue_tile((t + 1) & 1, (t + 1) * 32);
            asm volatile("cp.async.wait_group 1;" ::: "memory");
        } else {
            asm volatile("cp.async.wait_group 0;" ::: "memory");
        }
        __syncthreads();

        const uint32_t* As = &sA[(t & 1) * TILE_ELEMS];
        const uint32_t* Ws = &sW[(t & 1) * TILE_ELEMS];

#pragma unroll
        for (int kk = 0; kk < 4; kk++) {
            const int kb = kk * 8;
            uint32_t bfr[8][2];
#pragma unroll
            for (int j = 0; j < 8; j++) {
                int nrow = wn * 64 + j * 8 + gid;
                bfr[j][0] = Ws[nrow * SMS + kb + tig];
                bfr[j][1] = Ws[nrow * SMS + kb + tig + 4];
            }
            uint32_t afr[2][4];
#pragma unroll
            for (int i = 0; i < 2; i++) {
                int mrow = wm * 32 + i * 16 + gid;
                afr[i][0] = As[mrow * SMS + kb + tig];
                afr[i][1] = As[(mrow + 8) * SMS + kb + tig];
                afr[i][2] = As[mrow * SMS + kb + tig + 4];
                afr[i][3] = As[(mrow + 8) * SMS + kb + tig + 4];
            }
#pragma unroll
            for (int i = 0; i < 2; i++)
#pragma unroll
                for (int j = 0; j < 8; j++)
                    mma_tf32(acc[i][j], afr[i], bfr[j]);
        }
        __syncthreads();
    }

#pragma unroll
    for (int i = 0; i < 2; i++) {
        int row0 = bm + wm * 32 + i * 16 + gid;
#pragma unroll
        for (int j = 0; j < 8; j++) {
            int col = bn + wn * 64 + j * 8 + tig * 2;
            float b0 = bias[col], b1v = bias[col + 1];
            float v0 = acc[i][j][0] + b0;
            float v1 = acc[i][j][1] + b1v;
            float v2 = acc[i][j][2] + b0;
            float v3 = acc[i][j][3] + b1v;
            *reinterpret_cast<float2*>(&C[(size_t)row0 * N + col]) = make_float2(v0, v1);
            *reinterpret_cast<float2*>(&C[(size_t)(row0 + 8) * N + col]) = make_float2(v2, v3);
            *reinterpret_cast<float2*>(&Cr[(size_t)row0 * N + col])
                = make_float2(roundf_tf32(v0), roundf_tf32(v1));
            *reinterpret_cast<float2*>(&Cr[(size_t)(row0 + 8) * N + col])
                = make_float2(roundf_tf32(v2), roundf_tf32(v3));
        }
    }
}

// ============================================================
// MLP GEMM fused with w2 contraction:
// a1_tile = relu(relu(hxr) @ w1r^T + b1)   [128 x 128, registers only]
// dxy[bm+row, o] += sum_col a1_tile[row,col] * w2[o, bn+col]   (atomics)
// ============================================================
__global__ void __launch_bounds__(256, 2)
gemm_mlp(const float* __restrict__ A, const float* __restrict__ W,
         const float* __restrict__ b1g, const float* __restrict__ w2,
         float* __restrict__ dxy)
{
    extern __shared__ uint32_t sm[];
    uint32_t* sA = sm;
    uint32_t* sW = sm + 2 * TILE_ELEMS;
    __shared__ float sw2[4][128];
    __shared__ float sdxy[128][4];
    const int K = 512;

    const int tid  = threadIdx.x;
    const int warp = tid >> 5;
    const int lane = tid & 31;
    const int gid  = lane >> 2;
    const int tig  = lane & 3;
    const int wm   = warp >> 1;
    const int wn   = warp & 1;
    const int bm   = blockIdx.x * 128;
    const int bn   = blockIdx.y * 128;

    for (int i = tid; i < 512; i += 256) {
        sw2[i >> 7][i & 127] = w2[(size_t)(i >> 7) * 2048 + bn + (i & 127)];
        reinterpret_cast<float*>(sdxy)[i] = 0.f;
    }

    float acc[2][8][4];
#pragma unroll
    for (int i = 0; i < 2; i++)
#pragma unroll
        for (int j = 0; j < 8; j++)
#pragma unroll
            for (int r = 0; r < 4; r++) acc[i][j][r] = 0.f;

    auto issue_tile = [&](int s, int k0) {
#pragma unroll
        for (int it = 0; it < 4; it++) {
            int lin = tid + it * 256;
            int row = lin >> 3;
            int c4  = (lin & 7) * 4;
            cp16(&sW[s * TILE_ELEMS + row * SMS + c4],
                 &W[(size_t)(bn + row) * K + k0 + c4]);
            cp16(&sA[s * TILE_ELEMS + row * SMS + c4],
                 &A[(size_t)(bm + row) * K + k0 + c4]);
        }
        asm volatile("cp.async.commit_group;" ::: "memory");
    };

    const int T = K >> 5;
    issue_tile(0, 0);

    for (int t = 0; t < T; t++) {
        if (t + 1 < T) {
            issue_tile((t + 1) & 1, (t + 1) * 32);
            asm volatile("cp.async.wait_group 1;" ::: "memory");
        } else {
            asm volatile("cp.async.wait_group 0;" ::: "memory");
        }
        __syncthreads();

        const uint32_t* As = &sA[(t & 1) * TILE_ELEMS];
        const uint32_t* Ws = &sW[(t & 1) * TILE_ELEMS];

#pragma unroll
        for (int kk = 0; kk < 4; kk++) {
            const int kb = kk * 8;
            uint32_t bfr[8][2];
#pragma unroll
            for (int j = 0; j < 8; j++) {
                int nrow = wn * 64 + j * 8 + gid;
                bfr[j][0] = Ws[nrow * SMS + kb + tig];
                bfr[j][1] = Ws[nrow * SMS + kb + tig + 4];
            }
            uint32_t afr[2][4];
#pragma unroll
            for (int i = 0; i < 2; i++) {
                int mrow = wm * 32 + i * 16 + gid;
                afr[i][0] = As[mrow * SMS + kb + tig];
                afr[i][1] = As[(mrow + 8) * SMS + kb + tig];
                afr[i][2] = As[mrow * SMS + kb + tig + 4];
                afr[i][3] = As[(mrow + 8) * SMS + kb + tig + 4];
#pragma unroll
                for (int r = 0; r < 4; r++) {
                    float f = fmaxf(__uint_as_float(afr[i][r]), 0.f);
                    afr[i][r] = __float_as_uint(f);
                }
            }
#pragma unroll
            for (int i = 0; i < 2; i++)
#pragma unroll
                for (int j = 0; j < 8; j++)
                    mma_tf32(acc[i][j], afr[i], bfr[j]);
        }
        __syncthreads();
    }

    // ---- epilogue: contract a1 tile with w2 slice ----
    float p[2][2][4];
#pragma unroll
    for (int i = 0; i < 2; i++)
#pragma unroll
        for (int rr = 0; rr < 2; rr++)
#pragma unroll
            for (int o = 0; o < 4; o++) p[i][rr][o] = 0.f;

#pragma unroll
    for (int i = 0; i < 2; i++)
#pragma unroll
        for (int j = 0; j < 8; j++) {
            const int lc = wn * 64 + j * 8 + tig * 2;
            const float bb0 = b1g[bn + lc], bb1 = b1g[bn + lc + 1];
            const float a00 = fmaxf(acc[i][j][0] + bb0, 0.f);
            const float a01 = fmaxf(acc[i][j][1] + bb1, 0.f);
            const float a10 = fmaxf(acc[i][j][2] + bb0, 0.f);
            const float a11 = fmaxf(acc[i][j][3] + bb1, 0.f);
#pragma unroll
            for (int o = 0; o < 4; o++) {
                const float w0 = sw2[o][lc], w1 = sw2[o][lc + 1];
                p[i][0][o] += a00 * w0 + a01 * w1;
                p[i][1][o] += a10 * w0 + a11 * w1;
            }
        }

    // reduce over tig (4 lanes share a row within this warp's half)
#pragma unroll
    for (int i = 0; i < 2; i++)
#pragma unroll
        for (int rr = 0; rr < 2; rr++)
#pragma unroll
            for (int o = 0; o < 4; o++) {
                float v = p[i][rr][o];
                v += __shfl_xor_sync(0xFFFFFFFFu, v, 1);
                v += __shfl_xor_sync(0xFFFFFFFFu, v, 2);
                p[i][rr][o] = v;
            }
    if (tig == 0) {
#pragma unroll
        for (int i = 0; i < 2; i++)
#pragma unroll
            for (int rr = 0; rr < 2; rr++) {
                const int row = wm * 32 + i * 16 + rr * 8 + gid;
#pragma unroll
                for (int o = 0; o < 4; o++)
                    atomicAdd(&sdxy[row][o], p[i][rr][o]);
            }
    }
    __syncthreads();
    for (int i = tid; i < 512; i += 256) {
        const int row = i >> 2, o = i & 3;
        atomicAdd(&dxy[(size_t)(bm + row) * 4 + o], sdxy[row][o]);
    }
}

// ============================================================
// readout: xy += dxy + b2; out[:, step] = xy; dxy = 0
// ============================================================
__global__ void __launch_bounds__(256)
readout_kernel(float* __restrict__ xy, float* __restrict__ dxy,
               const float* __restrict__ b2, float* __restrict__ out, int step)
{
    int i = blockIdx.x * blockDim.x + threadIdx.x;
    if (i < B_) {
        float4 d  = reinterpret_cast<float4*>(dxy)[i];
        float4 xv = reinterpret_cast<float4*>(xy)[i];
        xv.x += d.x + b2[0];
        xv.y += d.y + b2[1];
        xv.z += d.z + b2[2];
        xv.w += d.w + b2[3];
        reinterpret_cast<float4*>(xy)[i] = xv;
        reinterpret_cast<float4*>(out)[(size_t)i * HOR_ + step] = xv;
        reinterpret_cast<float4*>(dxy)[i] = make_float4(0.f, 0.f, 0.f, 0.f);
    }
}

// ============================================================
// Launch
// ============================================================
extern "C" void kernel_launch(void* const* d_in, const int* in_sizes, int n_in,
                              void* d_out, int out_size)
{
    const float* pv   = (const float*)d_in[0];
    const float* ptf  = (const float*)d_in[1];
    const float* w_ih = (const float*)d_in[2];
    const float* w_hh = (const float*)d_in[3];
    const float* b_ih = (const float*)d_in[4];
    const float* b_hh = (const float*)d_in[5];
    const float* w_fc = (const float*)d_in[6];
    const float* b_fc = (const float*)d_in[7];
    const float* w1   = (const float*)d_in[8];
    const float* b1   = (const float*)d_in[9];
    const float* w2   = (const float*)d_in[10];
    const float* b2   = (const float*)d_in[11];
    float* out = (float*)d_out;

    float *h1, *hx, *xy, *dxy, *h1r, *h2r, *hxr, *ptfr, *whhr, *wfcr, *w1r;
    cudaGetSymbolAddress((void**)&h1,   g_h1);
    cudaGetSymbolAddress((void**)&hx,   g_hx);
    cudaGetSymbolAddress((void**)&xy,   g_xy);
    cudaGetSymbolAddress((void**)&dxy,  g_dxy);
    cudaGetSymbolAddress((void**)&h1r,  g_h1r);
    cudaGetSymbolAddress((void**)&h2r,  g_h2r);
    cudaGetSymbolAddress((void**)&hxr,  g_hxr);
    cudaGetSymbolAddress((void**)&ptfr, g_ptfr);
    cudaGetSymbolAddress((void**)&whhr, g_whhr);
    cudaGetSymbolAddress((void**)&wfcr, g_wfcr);
    cudaGetSymbolAddress((void**)&w1r,  g_w1r);

    cudaFuncSetAttribute(hh_fused,
        cudaFuncAttributeMaxDynamicSharedMemorySize, HH_SMEM_BYTES);
    cudaFuncSetAttribute(gemm_fc,
        cudaFuncAttributeMaxDynamicSharedMemorySize, GC_SMEM_BYTES);
    cudaFuncSetAttribute(gemm_mlp,
        cudaFuncAttributeMaxDynamicSharedMemorySize, GC_SMEM_BYTES);

    // ---- prep: round weights + ptf; zero xy, dxy ----
    round_kernel<<<(3 * H_ * H_ / 4 + 255) / 256, 256>>>(w_hh, whhr, 3 * H_ * H_ / 4);
    round_kernel<<<(H_ * 2 * H_ / 4 + 255) / 256, 256>>>(w_fc, wfcr, H_ * 2 * H_ / 4);
    round_kernel<<<(FF_ * H_ / 4 + 255) / 256, 256>>>(w1, w1r, FF_ * H_ / 4);
    round_kernel<<<(B_ * H_ / 4 + 255) / 256, 256>>>(ptf, ptfr, B_ * H_ / 4);
    zero_kernel<<<(B_ * OUT_ + 255) / 256, 256>>>(xy, B_ * OUT_);
    zero_kernel<<<(B_ * OUT_ + 255) / 256, 256>>>(dxy, B_ * OUT_);

    const dim3 gridHH(B_ / 128, H_ / 64);      // (128, 8)
    const dim3 gridFC(B_ / 128, H_ / 128);     // (128, 4)
    const dim3 gridM1(B_ / 128, FF_ / 128);    // (128, 16)

    for (int step = 0; step < HOR_; step++) {
        const float* hxin_r = (step == 0) ? ptfr : hxr;
        const float* hxin_f = (step == 0) ? ptf  : hx;

        // cell 1 (fused gate): h1 = GRUCell(xy, hx)
        hh_fused<<<gridHH, 256, HH_SMEM_BYTES>>>(
            hxin_r, whhr, hxin_f, xy, OUT_, w_ih, b_ih, b_hh, h1, h1r);

        // cell 2 (fused gate): h2 = GRUCell(pv[:,step], h1)
        hh_fused<<<gridHH, 256, HH_SMEM_BYTES>>>(
            h1r, whhr, h1, pv + step * OUT_, HOR_ * OUT_, w_ih, b_ih, b_hh,
            nullptr, h2r);

        // hx = concat(h1,h2) @ w_fc^T + b_fc  (dual write hx / hxr)
        gemm_fc<<<gridFC, 256, GC_SMEM_BYTES>>>(h1r, h2r, wfcr, b_fc, hx, hxr);

        // dxy += (relu(relu(hx)@w1^T+b1)) @ w2^T  (fused, atomic partials)
        gemm_mlp<<<gridM1, 256, GC_SMEM_BYTES>>>(hxr, w1r, b1, w2, dxy);

        // xy += dxy + b2 ; out[:,step] = xy ; dxy = 0
        readout_kernel<<<B_ / 256, 256>>>(xy, dxy, b2, out, step);
    }
}

// round 9
// speedup vs baseline: 4.6398x; 1.4960x over previous
#include <cuda_runtime.h>
#include <cuda_fp16.h>
#include <math.h>
#include <stdint.h>

#define B_   16384
#define H_   512
#define FF_  2048
#define OUT_ 4
#define HOR_ 5

// ---- scratch (device globals; no allocation) ----
__device__ float  g_h1[B_ * H_];      // cell-1 hidden, fp32 (gate h-term of cell 2)
__device__ float  g_hx[B_ * H_];      // fc output fp32 (gate h-term of next step)
__device__ float  g_xy[B_ * OUT_];
__device__ float  g_dxy[B_ * OUT_];   // MLP partial-sum accumulator
// fp16 copies (GEMM operands)
__device__ __half g_h1h[B_ * H_];
__device__ __half g_h2h[B_ * H_];
__device__ __half g_hxh[B_ * H_];
__device__ __half g_ptfh[B_ * H_];
__device__ __half g_whhh[3 * H_ * H_];
__device__ __half g_wfch[H_ * 2 * H_];
__device__ __half g_w1h[FF_ * H_];

// ============================================================
// helpers
// ============================================================
__device__ __forceinline__ void mma_f16(float c[4], const uint32_t a[4],
                                        const uint32_t b[2]) {
    asm volatile(
        "mma.sync.aligned.m16n8k16.row.col.f32.f16.f16.f32 "
        "{%0,%1,%2,%3}, {%4,%5,%6,%7}, {%8,%9}, {%0,%1,%2,%3};"
        : "+f"(c[0]), "+f"(c[1]), "+f"(c[2]), "+f"(c[3])
        : "r"(a[0]), "r"(a[1]), "r"(a[2]), "r"(a[3]),
          "r"(b[0]), "r"(b[1]));
}

__device__ __forceinline__ void cp16(void* smem_ptr, const void* gsrc) {
    uint32_t a = (uint32_t)__cvta_generic_to_shared(smem_ptr);
    asm volatile("cp.async.cg.shared.global [%0], [%1], 16;"
                 :: "r"(a), "l"(gsrc));
}

__device__ __forceinline__ float sigmoidf_(float x) {
    return 1.f / (1.f + expf(-x));
}

// ============================================================
// prep kernels
// ============================================================
__global__ void cvt_kernel(const float* __restrict__ src,
                           __half* __restrict__ dst, int n4) {
    int i = blockIdx.x * blockDim.x + threadIdx.x;
    if (i < n4) {
        float4 v = reinterpret_cast<const float4*>(src)[i];
        __half2 lo = __floats2half2_rn(v.x, v.y);
        __half2 hi = __floats2half2_rn(v.z, v.w);
        reinterpret_cast<__half2*>(dst)[i * 2]     = lo;
        reinterpret_cast<__half2*>(dst)[i * 2 + 1] = hi;
    }
}

__global__ void zero_kernel(float* __restrict__ p, int n) {
    int i = blockIdx.x * blockDim.x + threadIdx.x;
    if (i < n) p[i] = 0.f;
}

#define SMSH 40   // smem row pitch in halves: 32 + 8 pad (80B, 16B-aligned)

// ============================================================
// Gate-fused HH GEMM (fp16 operands).
// grid (B/128, 512/64).  CTA computes gh_r/gh_z/gh_n accumulators for
// [128 batch x 64 gate-cols].  Epilogue applies the full GRU cell.
// 256 threads (8 warps 4m x 2n), warp tile 32x32 per gate, 2-stage cp.async.
// BK=32 -> 2 mma k-steps (k16) per tile.
// ============================================================
#define HH_STAGE_H (320 * SMSH)              // A 128 rows + W 192 rows (halves)
#define HH_SMEM_BYTES (2u * HH_STAGE_H * 2u)

__global__ void __launch_bounds__(256)
hh_fused(const __half* __restrict__ Ah, const __half* __restrict__ Whh,
         const float* __restrict__ hf, const float* __restrict__ x, int xstride,
         const float* __restrict__ w_ih, const float* __restrict__ b_ih,
         const float* __restrict__ b_hh,
         float* __restrict__ hout, __half* __restrict__ houth)
{
    extern __shared__ __half smh[];

    const int tid  = threadIdx.x;
    const int warp = tid >> 5;
    const int lane = tid & 31;
    const int gid  = lane >> 2;
    const int tig  = lane & 3;
    const int wm   = warp >> 1;          // 0..3
    const int wn   = warp & 1;           // 0..1
    const int bm   = blockIdx.x * 128;
    const int bn   = blockIdx.y * 64;

    float acc[3][2][4][4];
#pragma unroll
    for (int g = 0; g < 3; g++)
#pragma unroll
        for (int i = 0; i < 2; i++)
#pragma unroll
            for (int j = 0; j < 4; j++)
#pragma unroll
                for (int r = 0; r < 4; r++) acc[g][i][j][r] = 0.f;

    auto issue = [&](int t) {
        const int s  = t & 1;
        const int k0 = t * 32;
        __half* base = smh + s * HH_STAGE_H;
#pragma unroll
        for (int it = 0; it < 2; it++) {            // A: 128 rows x 4 chunks
            int lin = tid + it * 256;
            int row = lin >> 2, j = lin & 3;
            cp16(&base[row * SMSH + j * 8],
                 &Ah[(size_t)(bm + row) * 512 + k0 + j * 8]);
        }
#pragma unroll
        for (int it = 0; it < 3; it++) {            // W: 192 rows x 4 chunks
            int lin = tid + it * 256;
            int row = lin >> 2, j = lin & 3;
            int g = row >> 6, lr = row & 63;
            cp16(&base[(128 + row) * SMSH + j * 8],
                 &Whh[(size_t)(g * 512 + bn + lr) * 512 + k0 + j * 8]);
        }
        asm volatile("cp.async.commit_group;" ::: "memory");
    };

    issue(0);
    for (int t = 0; t < 16; t++) {
        if (t + 1 < 16) {
            issue(t + 1);
            asm volatile("cp.async.wait_group 1;" ::: "memory");
        } else {
            asm volatile("cp.async.wait_group 0;" ::: "memory");
        }
        __syncthreads();

        const uint32_t* sa = reinterpret_cast<const uint32_t*>(smh + (t & 1) * HH_STAGE_H);
        const uint32_t* sw = sa + 128 * (SMSH / 2);

#pragma unroll
        for (int kk = 0; kk < 2; kk++) {            // 2 x k16
            const int kw = kk * 8;                  // u32-word offset
            uint32_t afr[2][4];
#pragma unroll
            for (int i = 0; i < 2; i++) {
                int mrow = wm * 32 + i * 16 + gid;
                afr[i][0] = sa[mrow * (SMSH/2) + kw + tig];
                afr[i][1] = sa[(mrow + 8) * (SMSH/2) + kw + tig];
                afr[i][2] = sa[mrow * (SMSH/2) + kw + tig + 4];
                afr[i][3] = sa[(mrow + 8) * (SMSH/2) + kw + tig + 4];
            }
            uint32_t bfr[3][4][2];
#pragma unroll
            for (int g = 0; g < 3; g++)
#pragma unroll
                for (int j = 0; j < 4; j++) {
                    int nrow = g * 64 + wn * 32 + j * 8 + gid;
                    bfr[g][j][0] = sw[nrow * (SMSH/2) + kw + tig];
                    bfr[g][j][1] = sw[nrow * (SMSH/2) + kw + tig + 4];
                }
#pragma unroll
            for (int g = 0; g < 3; g++)
#pragma unroll
                for (int i = 0; i < 2; i++)
#pragma unroll
                    for (int j = 0; j < 4; j++)
                        mma_f16(acc[g][i][j], afr[i], bfr[g][j]);
        }
        __syncthreads();
    }

    // ---- fused gate epilogue ----
#pragma unroll
    for (int i = 0; i < 2; i++) {
        const int r0 = bm + wm * 32 + i * 16 + gid;
        const int r1 = r0 + 8;
        const float4 xv0 = *reinterpret_cast<const float4*>(&x[(size_t)r0 * xstride]);
        const float4 xv1 = *reinterpret_cast<const float4*>(&x[(size_t)r1 * xstride]);
#pragma unroll
        for (int j = 0; j < 4; j++) {
            const int col = bn + wn * 32 + j * 8 + tig * 2;
            const float2 hp0 = *reinterpret_cast<const float2*>(&hf[(size_t)r0 * 512 + col]);
            const float2 hp1 = *reinterpret_cast<const float2*>(&hf[(size_t)r1 * 512 + col]);
            float res[2][2];
#pragma unroll
            for (int c = 0; c < 2; c++) {
                const int cc = col + c;
                const float4 wr  = *reinterpret_cast<const float4*>(&w_ih[(size_t)cc * 4]);
                const float4 wz  = *reinterpret_cast<const float4*>(&w_ih[(size_t)(cc + 512) * 4]);
                const float4 wnn = *reinterpret_cast<const float4*>(&w_ih[(size_t)(cc + 1024) * 4]);
                const float bir = b_ih[cc], biz = b_ih[cc + 512], bin = b_ih[cc + 1024];
                const float bhr = b_hh[cc], bhz = b_hh[cc + 512], bhn = b_hh[cc + 1024];
#pragma unroll
                for (int rr = 0; rr < 2; rr++) {
                    const float4 xv = rr ? xv1 : xv0;
                    float gir = bir + xv.x*wr.x + xv.y*wr.y + xv.z*wr.z + xv.w*wr.w;
                    float giz = biz + xv.x*wz.x + xv.y*wz.y + xv.z*wz.z + xv.w*wz.w;
                    float gin = bin + xv.x*wnn.x + xv.y*wnn.y + xv.z*wnn.z + xv.w*wnn.w;
                    float ghr = acc[0][i][j][rr * 2 + c] + bhr;
                    float ghz = acc[1][i][j][rr * 2 + c] + bhz;
                    float ghn = acc[2][i][j][rr * 2 + c] + bhn;
                    float rg = sigmoidf_(gir + ghr);
                    float zg = sigmoidf_(giz + ghz);
                    float ng = tanhf(gin + rg * ghn);
                    float hprev = rr ? (c ? hp1.y : hp1.x) : (c ? hp0.y : hp0.x);
                    res[rr][c] = (1.f - zg) * ng + zg * hprev;
                }
            }
            if (hout) {
                *reinterpret_cast<float2*>(&hout[(size_t)r0 * 512 + col])
                    = make_float2(res[0][0], res[0][1]);
                *reinterpret_cast<float2*>(&hout[(size_t)r1 * 512 + col])
                    = make_float2(res[1][0], res[1][1]);
            }
            *reinterpret_cast<__half2*>(&houth[(size_t)r0 * 512 + col])
                = __floats2half2_rn(res[0][0], res[0][1]);
            *reinterpret_cast<__half2*>(&houth[(size_t)r1 * 512 + col])
                = __floats2half2_rn(res[1][0], res[1][1]);
        }
    }
}

// ============================================================
// fc GEMM: hx = concat(h1h,h2h) @ wfch^T + b_fc   (fp16 operands)
// DUAL write: hx fp32 + hxh fp16.  BM=BN=128, BK=32, 2-stage cp.async.
// ============================================================
#define TILE_H (128 * SMSH)
#define GC_SMEM_BYTES (4u * TILE_H * 2u)

__global__ void __launch_bounds__(256, 2)
gemm_fc(const __half* __restrict__ A, const __half* __restrict__ A2,
        const __half* __restrict__ W, const float* __restrict__ bias,
        float* __restrict__ C, __half* __restrict__ Ch)
{
    extern __shared__ __half smh[];
    __half* sAh = smh;
    __half* sWh = smh + 2 * TILE_H;
    const int K = 1024, N = 512;

    const int tid  = threadIdx.x;
    const int warp = tid >> 5;
    const int lane = tid & 31;
    const int gid  = lane >> 2;
    const int tig  = lane & 3;
    const int wm   = warp >> 1;
    const int wn   = warp & 1;
    const int bm   = blockIdx.x * 128;
    const int bn   = blockIdx.y * 128;

    float acc[2][8][4];
#pragma unroll
    for (int i = 0; i < 2; i++)
#pragma unroll
        for (int j = 0; j < 8; j++)
#pragma unroll
            for (int r = 0; r < 4; r++) acc[i][j][r] = 0.f;

    auto issue_tile = [&](int s, int k0) {
#pragma unroll
        for (int it = 0; it < 2; it++) {
            int lin = tid + it * 256;
            int row = lin >> 2, j = lin & 3;
            cp16(&sWh[s * TILE_H + row * SMSH + j * 8],
                 &W[(size_t)(bn + row) * K + k0 + j * 8]);
            const __half* asrc = (k0 < 512)
                ? &A [(size_t)(bm + row) * 512 + k0 + j * 8]
                : &A2[(size_t)(bm + row) * 512 + (k0 - 512) + j * 8];
            cp16(&sAh[s * TILE_H + row * SMSH + j * 8], asrc);
        }
        asm volatile("cp.async.commit_group;" ::: "memory");
    };

    const int T = K >> 5;
    issue_tile(0, 0);

    for (int t = 0; t < T; t++) {
        if (t + 1 < T) {
            issue_tile((t + 1) & 1, (t + 1) * 32);
            asm volatile("cp.async.wait_group 1;" ::: "memory");
        } else {
            asm volatile("cp.async.wait_group 0;" ::: "memory");
        }
        __syncthreads();

        const uint32_t* As = reinterpret_cast<const uint32_t*>(&sAh[(t & 1) * TILE_H]);
        const uint32_t* Ws = reinterpret_cast<const uint32_t*>(&sWh[(t & 1) * TILE_H]);

#pragma unroll
        for (int kk = 0; kk < 2; kk++) {
            const int kw = kk * 8;
            uint32_t bfr[8][2];
#pragma unroll
            for (int j = 0; j < 8; j++) {
                int nrow = wn * 64 + j * 8 + gid;
                bfr[j][0] = Ws[nrow * (SMSH/2) + kw + tig];
                bfr[j][1] = Ws[nrow * (SMSH/2) + kw + tig + 4];
            }
            uint32_t afr[2][4];
#pragma unroll
            for (int i = 0; i < 2; i++) {
                int mrow = wm * 32 + i * 16 + gid;
                afr[i][0] = As[mrow * (SMSH/2) + kw + tig];
                afr[i][1] = As[(mrow + 8) * (SMSH/2) + kw + tig];
                afr[i][2] = As[mrow * (SMSH/2) + kw + tig + 4];
                afr[i][3] = As[(mrow + 8) * (SMSH/2) + kw + tig + 4];
            }
#pragma unroll
            for (int i = 0; i < 2; i++)
#pragma unroll
                for (int j = 0; j < 8; j++)
                    mma_f16(acc[i][j], afr[i], bfr[j]);
        }
        __syncthreads();
    }

#pragma unroll
    for (int i = 0; i < 2; i++) {
        int row0 = bm + wm * 32 + i * 16 + gid;
#pragma unroll
        for (int j = 0; j < 8; j++) {
            int col = bn + wn * 64 + j * 8 + tig * 2;
            float b0 = bias[col], b1v = bias[col + 1];
            float v0 = acc[i][j][0] + b0;
            float v1 = acc[i][j][1] + b1v;
            float v2 = acc[i][j][2] + b0;
            float v3 = acc[i][j][3] + b1v;
            *reinterpret_cast<float2*>(&C[(size_t)row0 * N + col]) = make_float2(v0, v1);
            *reinterpret_cast<float2*>(&C[(size_t)(row0 + 8) * N + col]) = make_float2(v2, v3);
            *reinterpret_cast<__half2*>(&Ch[(size_t)row0 * N + col])
                = __floats2half2_rn(v0, v1);
            *reinterpret_cast<__half2*>(&Ch[(size_t)(row0 + 8) * N + col])
                = __floats2half2_rn(v2, v3);
        }
    }
}

// ============================================================
// MLP GEMM fused with w2 contraction (fp16 operands):
// a1_tile = relu(relu(hxh) @ w1h^T + b1)   [128 x 128, registers only]
// dxy[bm+row, o] += sum_col a1_tile[row,col] * w2[o, bn+col]
// ============================================================
__global__ void __launch_bounds__(256, 2)
gemm_mlp(const __half* __restrict__ A, const __half* __restrict__ W,
         const float* __restrict__ b1g, const float* __restrict__ w2,
         float* __restrict__ dxy)
{
    extern __shared__ __half smh[];
    __half* sAh = smh;
    __half* sWh = smh + 2 * TILE_H;
    __shared__ float sw2[4][128];
    __shared__ float sdxy[128][4];
    const int K = 512;

    const int tid  = threadIdx.x;
    const int warp = tid >> 5;
    const int lane = tid & 31;
    const int gid  = lane >> 2;
    const int tig  = lane & 3;
    const int wm   = warp >> 1;
    const int wn   = warp & 1;
    const int bm   = blockIdx.x * 128;
    const int bn   = blockIdx.y * 128;

    for (int i = tid; i < 512; i += 256) {
        sw2[i >> 7][i & 127] = w2[(size_t)(i >> 7) * 2048 + bn + (i & 127)];
        reinterpret_cast<float*>(sdxy)[i] = 0.f;
    }

    float acc[2][8][4];
#pragma unroll
    for (int i = 0; i < 2; i++)
#pragma unroll
        for (int j = 0; j < 8; j++)
#pragma unroll
            for (int r = 0; r < 4; r++) acc[i][j][r] = 0.f;

    auto issue_tile = [&](int s, int k0) {
#pragma unroll
        for (int it = 0; it < 2; it++) {
            int lin = tid + it * 256;
            int row = lin >> 2, j = lin & 3;
            cp16(&sWh[s * TILE_H + row * SMSH + j * 8],
                 &W[(size_t)(bn + row) * K + k0 + j * 8]);
            cp16(&sAh[s * TILE_H + row * SMSH + j * 8],
                 &A[(size_t)(bm + row) * K + k0 + j * 8]);
        }
        asm volatile("cp.async.commit_group;" ::: "memory");
    };

    const int T = K >> 5;
    issue_tile(0, 0);

    const __half2 z2 = __floats2half2_rn(0.f, 0.f);

    for (int t = 0; t < T; t++) {
        if (t + 1 < T) {
            issue_tile((t + 1) & 1, (t + 1) * 32);
            asm volatile("cp.async.wait_group 1;" ::: "memory");
        } else {
            asm volatile("cp.async.wait_group 0;" ::: "memory");
        }
        __syncthreads();

        const uint32_t* As = reinterpret_cast<const uint32_t*>(&sAh[(t & 1) * TILE_H]);
        const uint32_t* Ws = reinterpret_cast<const uint32_t*>(&sWh[(t & 1) * TILE_H]);

#pragma unroll
        for (int kk = 0; kk < 2; kk++) {
            const int kw = kk * 8;
            uint32_t bfr[8][2];
#pragma unroll
            for (int j = 0; j < 8; j++) {
                int nrow = wn * 64 + j * 8 + gid;
                bfr[j][0] = Ws[nrow * (SMSH/2) + kw + tig];
                bfr[j][1] = Ws[nrow * (SMSH/2) + kw + tig + 4];
            }
            uint32_t afr[2][4];
#pragma unroll
            for (int i = 0; i < 2; i++) {
                int mrow = wm * 32 + i * 16 + gid;
                afr[i][0] = As[mrow * (SMSH/2) + kw + tig];
                afr[i][1] = As[(mrow + 8) * (SMSH/2) + kw + tig];
                afr[i][2] = As[mrow * (SMSH/2) + kw + tig + 4];
                afr[i][3] = As[(mrow + 8) * (SMSH/2) + kw + tig + 4];
#pragma unroll
                for (int r = 0; r < 4; r++) {
                    __half2 h = *reinterpret_cast<__half2*>(&afr[i][r]);
                    h = __hmax2(h, z2);
                    afr[i][r] = *reinterpret_cast<uint32_t*>(&h);
                }
            }
#pragma unroll
            for (int i = 0; i < 2; i++)
#pragma unroll
                for (int j = 0; j < 8; j++)
                    mma_f16(acc[i][j], afr[i], bfr[j]);
        }
        __syncthreads();
    }

    // ---- epilogue: contract a1 tile with w2 slice ----
    float p[2][2][4];
#pragma unroll
    for (int i = 0; i < 2; i++)
#pragma unroll
        for (int rr = 0; rr < 2; rr++)
#pragma unroll
            for (int o = 0; o < 4; o++) p[i][rr][o] = 0.f;

#pragma unroll
    for (int i = 0; i < 2; i++)
#pragma unroll
        for (int j = 0; j < 8; j++) {
            const int lc = wn * 64 + j * 8 + tig * 2;
            const float bb0 = b1g[bn + lc], bb1 = b1g[bn + lc + 1];
            const float a00 = fmaxf(acc[i][j][0] + bb0, 0.f);
            const float a01 = fmaxf(acc[i][j][1] + bb1, 0.f);
            const float a10 = fmaxf(acc[i][j][2] + bb0, 0.f);
            const float a11 = fmaxf(acc[i][j][3] + bb1, 0.f);
#pragma unroll
            for (int o = 0; o < 4; o++) {
                const float w0 = sw2[o][lc], w1 = sw2[o][lc + 1];
                p[i][0][o] += a00 * w0 + a01 * w1;
                p[i][1][o] += a10 * w0 + a11 * w1;
            }
        }

#pragma unroll
    for (int i = 0; i < 2; i++)
#pragma unroll
        for (int rr = 0; rr < 2; rr++)
#pragma unroll
            for (int o = 0; o < 4; o++) {
                float v = p[i][rr][o];
                v += __shfl_xor_sync(0xFFFFFFFFu, v, 1);
                v += __shfl_xor_sync(0xFFFFFFFFu, v, 2);
                p[i][rr][o] = v;
            }
    if (tig == 0) {
#pragma unroll
        for (int i = 0; i < 2; i++)
#pragma unroll
            for (int rr = 0; rr < 2; rr++) {
                const int row = wm * 32 + i * 16 + rr * 8 + gid;
#pragma unroll
                for (int o = 0; o < 4; o++)
                    atomicAdd(&sdxy[row][o], p[i][rr][o]);
            }
    }
    __syncthreads();
    for (int i = tid; i < 512; i += 256) {
        const int row = i >> 2, o = i & 3;
        atomicAdd(&dxy[(size_t)(bm + row) * 4 + o], sdxy[row][o]);
    }
}

// ============================================================
// readout: xy += dxy + b2; out[:, step] = xy; dxy = 0
// ============================================================
__global__ void __launch_bounds__(256)
readout_kernel(float* __restrict__ xy, float* __restrict__ dxy,
               const float* __restrict__ b2, float* __restrict__ out, int step)
{
    int i = blockIdx.x * blockDim.x + threadIdx.x;
    if (i < B_) {
        float4 d  = reinterpret_cast<float4*>(dxy)[i];
        float4 xv = reinterpret_cast<float4*>(xy)[i];
        xv.x += d.x + b2[0];
        xv.y += d.y + b2[1];
        xv.z += d.z + b2[2];
        xv.w += d.w + b2[3];
        reinterpret_cast<float4*>(xy)[i] = xv;
        reinterpret_cast<float4*>(out)[(size_t)i * HOR_ + step] = xv;
        reinterpret_cast<float4*>(dxy)[i] = make_float4(0.f, 0.f, 0.f, 0.f);
    }
}

// ============================================================
// Launch
// ============================================================
extern "C" void kernel_launch(void* const* d_in, const int* in_sizes, int n_in,
                              void* d_out, int out_size)
{
    const float* pv   = (const float*)d_in[0];
    const float* ptf  = (const float*)d_in[1];
    const float* w_ih = (const float*)d_in[2];
    const float* w_hh = (const float*)d_in[3];
    const float* b_ih = (const float*)d_in[4];
    const float* b_hh = (const float*)d_in[5];
    const float* w_fc = (const float*)d_in[6];
    const float* b_fc = (const float*)d_in[7];
    const float* w1   = (const float*)d_in[8];
    const float* b1   = (const float*)d_in[9];
    const float* w2   = (const float*)d_in[10];
    const float* b2   = (const float*)d_in[11];
    float* out = (float*)d_out;

    float *h1, *hx, *xy, *dxy;
    __half *h1h, *h2h, *hxh, *ptfh, *whhh, *wfch, *w1h;
    cudaGetSymbolAddress((void**)&h1,   g_h1);
    cudaGetSymbolAddress((void**)&hx,   g_hx);
    cudaGetSymbolAddress((void**)&xy,   g_xy);
    cudaGetSymbolAddress((void**)&dxy,  g_dxy);
    cudaGetSymbolAddress((void**)&h1h,  g_h1h);
    cudaGetSymbolAddress((void**)&h2h,  g_h2h);
    cudaGetSymbolAddress((void**)&hxh,  g_hxh);
    cudaGetSymbolAddress((void**)&ptfh, g_ptfh);
    cudaGetSymbolAddress((void**)&whhh, g_whhh);
    cudaGetSymbolAddress((void**)&wfch, g_wfch);
    cudaGetSymbolAddress((void**)&w1h,  g_w1h);

    cudaFuncSetAttribute(hh_fused,
        cudaFuncAttributeMaxDynamicSharedMemorySize, HH_SMEM_BYTES);
    cudaFuncSetAttribute(gemm_fc,
        cudaFuncAttributeMaxDynamicSharedMemorySize, GC_SMEM_BYTES);
    cudaFuncSetAttribute(gemm_mlp,
        cudaFuncAttributeMaxDynamicSharedMemorySize, GC_SMEM_BYTES);

    // ---- prep: convert weights + ptf to fp16; zero xy, dxy ----
    cvt_kernel<<<(3 * H_ * H_ / 4 + 255) / 256, 256>>>(w_hh, whhh, 3 * H_ * H_ / 4);
    cvt_kernel<<<(H_ * 2 * H_ / 4 + 255) / 256, 256>>>(w_fc, wfch, H_ * 2 * H_ / 4);
    cvt_kernel<<<(FF_ * H_ / 4 + 255) / 256, 256>>>(w1, w1h, FF_ * H_ / 4);
    cvt_kernel<<<(B_ * H_ / 4 + 255) / 256, 256>>>(ptf, ptfh, B_ * H_ / 4);
    zero_kernel<<<(B_ * OUT_ + 255) / 256, 256>>>(xy, B_ * OUT_);
    zero_kernel<<<(B_ * OUT_ + 255) / 256, 256>>>(dxy, B_ * OUT_);

    const dim3 gridHH(B_ / 128, H_ / 64);      // (128, 8)
    const dim3 gridFC(B_ / 128, H_ / 128);     // (128, 4)
    const dim3 gridM1(B_ / 128, FF_ / 128);    // (128, 16)

    for (int step = 0; step < HOR_; step++) {
        const __half* hxin_h = (step == 0) ? ptfh : hxh;
        const float*  hxin_f = (step == 0) ? ptf  : hx;

        // cell 1 (fused gate): h1 = GRUCell(xy, hx)
        hh_fused<<<gridHH, 256, HH_SMEM_BYTES>>>(
            hxin_h, whhh, hxin_f, xy, OUT_, w_ih, b_ih, b_hh, h1, h1h);

        // cell 2 (fused gate): h2 = GRUCell(pv[:,step], h1)
        hh_fused<<<gridHH, 256, HH_SMEM_BYTES>>>(
            h1h, whhh, h1, pv + step * OUT_, HOR_ * OUT_, w_ih, b_ih, b_hh,
            nullptr, h2h);

        // hx = concat(h1,h2) @ w_fc^T + b_fc  (dual write hx / hxh)
        gemm_fc<<<gridFC, 256, GC_SMEM_BYTES>>>(h1h, h2h, wfch, b_fc, hx, hxh);

        // dxy += (relu(relu(hx)@w1^T+b1)) @ w2^T  (fused, atomic partials)
        gemm_mlp<<<gridM1, 256, GC_SMEM_BYTES>>>(hxh, w1h, b1, w2, dxy);

        // xy += dxy + b2 ; out[:,step] = xy ; dxy = 0
        readout_kernel<<<B_ / 256, 256>>>(xy, dxy, b2, out, step);
    }
}

// round 10
// speedup vs baseline: 4.8121x; 1.0371x over previous
#include <cuda_runtime.h>
#include <cuda_fp16.h>
#include <math.h>
#include <stdint.h>

#define B_   16384
#define H_   512
#define FF_  2048
#define OUT_ 4
#define HOR_ 5

// ---- scratch (device globals; no allocation) ----
__device__ float  g_h1[B_ * H_];      // cell-1 hidden, fp32
__device__ float  g_hx[B_ * H_];      // fc output fp32
__device__ float  g_xy[B_ * OUT_];
__device__ float  g_dxy[B_ * OUT_];
// fp16 copies (GEMM operands)
__device__ __half g_h1h[B_ * H_];
__device__ __half g_h2h[B_ * H_];
__device__ __half g_hxh[B_ * H_];     // hx (no relu)   -> next-step HH
__device__ __half g_hxRh[B_ * H_];    // relu(hx)       -> MLP
__device__ __half g_ptfh[B_ * H_];
__device__ __half g_whhh[3 * H_ * H_];
__device__ __half g_wfch[H_ * 2 * H_];
__device__ __half g_w1h[FF_ * H_];

// ============================================================
// helpers
// ============================================================
__device__ __forceinline__ void mma_f16(float c[4], const uint32_t a[4],
                                        const uint32_t b[2]) {
    asm volatile(
        "mma.sync.aligned.m16n8k16.row.col.f32.f16.f16.f32 "
        "{%0,%1,%2,%3}, {%4,%5,%6,%7}, {%8,%9}, {%0,%1,%2,%3};"
        : "+f"(c[0]), "+f"(c[1]), "+f"(c[2]), "+f"(c[3])
        : "r"(a[0]), "r"(a[1]), "r"(a[2]), "r"(a[3]),
          "r"(b[0]), "r"(b[1]));
}

__device__ __forceinline__ void ldsm_x4(uint32_t r[4], uint32_t saddr) {
    asm volatile("ldmatrix.sync.aligned.m8n8.x4.shared.b16 {%0,%1,%2,%3}, [%4];"
                 : "=r"(r[0]), "=r"(r[1]), "=r"(r[2]), "=r"(r[3])
                 : "r"(saddr));
}

__device__ __forceinline__ void cp16(void* smem_ptr, const void* gsrc) {
    uint32_t a = (uint32_t)__cvta_generic_to_shared(smem_ptr);
    asm volatile("cp.async.cg.shared.global [%0], [%1], 16;"
                 :: "r"(a), "l"(gsrc));
}

__device__ __forceinline__ float sigmoidf_(float x) {
    return 1.f / (1.f + expf(-x));
}

// ============================================================
// prep kernels
// ============================================================
__global__ void cvt_kernel(const float* __restrict__ src,
                           __half* __restrict__ dst, int n4) {
    int i = blockIdx.x * blockDim.x + threadIdx.x;
    if (i < n4) {
        float4 v = reinterpret_cast<const float4*>(src)[i];
        reinterpret_cast<__half2*>(dst)[i * 2]     = __floats2half2_rn(v.x, v.y);
        reinterpret_cast<__half2*>(dst)[i * 2 + 1] = __floats2half2_rn(v.z, v.w);
    }
}

__global__ void zero_kernel(float* __restrict__ p, int n) {
    int i = blockIdx.x * blockDim.x + threadIdx.x;
    if (i < n) p[i] = 0.f;
}

#define SMSH 40   // smem row pitch in halves: 32 + 8 pad (80B)

// ============================================================
// Gate-fused HH GEMM (fp16, ldmatrix).
// grid (B/128, 512/64).  256 threads, warp tile 32x32 per gate,
// 2-stage cp.async, BK=32 (2 k16 steps per tile).
// ============================================================
#define HH_STAGE_H (320 * SMSH)              // A 128 rows + W 192 rows
#define HH_SMEM_BYTES (2u * HH_STAGE_H * 2u)

__global__ void __launch_bounds__(256)
hh_fused(const __half* __restrict__ Ah, const __half* __restrict__ Whh,
         const float* __restrict__ hf, const float* __restrict__ x, int xstride,
         const float* __restrict__ w_ih, const float* __restrict__ b_ih,
         const float* __restrict__ b_hh,
         float* __restrict__ hout, __half* __restrict__ houth)
{
    extern __shared__ __half smh[];

    const int tid  = threadIdx.x;
    const int warp = tid >> 5;
    const int lane = tid & 31;
    const int gid  = lane >> 2;
    const int tig  = lane & 3;
    const int wm   = warp >> 1;          // 0..3
    const int wn   = warp & 1;           // 0..1
    const int bm   = blockIdx.x * 128;
    const int bn   = blockIdx.y * 64;

    const uint32_t sbase = (uint32_t)__cvta_generic_to_shared(smh);
    // ldmatrix per-lane sub-addressing
    const int la_row = ((lane & 8) ? 8 : 0) + (lane & 7);  // A: row within m16
    const int la_k   = (lane & 16) ? 8 : 0;                // A: k within k16
    const int lb_n   = ((lane & 16) ? 8 : 0) + (lane & 7); // B: n within n16 pair
    const int lb_k   = (lane & 8) ? 8 : 0;                 // B: k within k16

    float acc[3][2][4][4];
#pragma unroll
    for (int g = 0; g < 3; g++)
#pragma unroll
        for (int i = 0; i < 2; i++)
#pragma unroll
            for (int j = 0; j < 4; j++)
#pragma unroll
                for (int r = 0; r < 4; r++) acc[g][i][j][r] = 0.f;

    auto issue = [&](int t) {
        const int s  = t & 1;
        const int k0 = t * 32;
        __half* base = smh + s * HH_STAGE_H;
#pragma unroll
        for (int it = 0; it < 2; it++) {            // A: 128 rows x 4 chunks
            int lin = tid + it * 256;
            int row = lin >> 2, j = lin & 3;
            cp16(&base[row * SMSH + j * 8],
                 &Ah[(size_t)(bm + row) * 512 + k0 + j * 8]);
        }
#pragma unroll
        for (int it = 0; it < 3; it++) {            // W: 192 rows x 4 chunks
            int lin = tid + it * 256;
            int row = lin >> 2, j = lin & 3;
            int g = row >> 6, lr = row & 63;
            cp16(&base[(128 + row) * SMSH + j * 8],
                 &Whh[(size_t)(g * 512 + bn + lr) * 512 + k0 + j * 8]);
        }
        asm volatile("cp.async.commit_group;" ::: "memory");
    };

    issue(0);
    for (int t = 0; t < 16; t++) {
        if (t + 1 < 16) {
            issue(t + 1);
            asm volatile("cp.async.wait_group 1;" ::: "memory");
        } else {
            asm volatile("cp.async.wait_group 0;" ::: "memory");
        }
        __syncthreads();

        const uint32_t st = sbase + (uint32_t)((t & 1) * HH_STAGE_H) * 2u;

#pragma unroll
        for (int kk = 0; kk < 2; kk++) {
            uint32_t afr[2][4];
#pragma unroll
            for (int i = 0; i < 2; i++) {
                uint32_t addr = st + (uint32_t)(
                    (wm * 32 + i * 16 + la_row) * SMSH + kk * 16 + la_k) * 2u;
                ldsm_x4(afr[i], addr);
            }
            uint32_t bfr[3][4][2];
#pragma unroll
            for (int g = 0; g < 3; g++)
#pragma unroll
                for (int jp = 0; jp < 2; jp++) {
                    uint32_t r[4];
                    uint32_t addr = st + (uint32_t)(
                        (128 + g * 64 + wn * 32 + jp * 16 + lb_n) * SMSH
                        + kk * 16 + lb_k) * 2u;
                    ldsm_x4(r, addr);
                    bfr[g][jp * 2][0]     = r[0]; bfr[g][jp * 2][1]     = r[1];
                    bfr[g][jp * 2 + 1][0] = r[2]; bfr[g][jp * 2 + 1][1] = r[3];
                }
#pragma unroll
            for (int g = 0; g < 3; g++)
#pragma unroll
                for (int i = 0; i < 2; i++)
#pragma unroll
                    for (int j = 0; j < 4; j++)
                        mma_f16(acc[g][i][j], afr[i], bfr[g][j]);
        }
        __syncthreads();
    }

    // ---- fused gate epilogue ----
#pragma unroll
    for (int i = 0; i < 2; i++) {
        const int r0 = bm + wm * 32 + i * 16 + gid;
        const int r1 = r0 + 8;
        const float4 xv0 = *reinterpret_cast<const float4*>(&x[(size_t)r0 * xstride]);
        const float4 xv1 = *reinterpret_cast<const float4*>(&x[(size_t)r1 * xstride]);
#pragma unroll
        for (int j = 0; j < 4; j++) {
            const int col = bn + wn * 32 + j * 8 + tig * 2;
            const float2 hp0 = *reinterpret_cast<const float2*>(&hf[(size_t)r0 * 512 + col]);
            const float2 hp1 = *reinterpret_cast<const float2*>(&hf[(size_t)r1 * 512 + col]);
            float res[2][2];
#pragma unroll
            for (int c = 0; c < 2; c++) {
                const int cc = col + c;
                const float4 wr  = *reinterpret_cast<const float4*>(&w_ih[(size_t)cc * 4]);
                const float4 wz  = *reinterpret_cast<const float4*>(&w_ih[(size_t)(cc + 512) * 4]);
                const float4 wnn = *reinterpret_cast<const float4*>(&w_ih[(size_t)(cc + 1024) * 4]);
                const float bir = b_ih[cc], biz = b_ih[cc + 512], bin = b_ih[cc + 1024];
                const float bhr = b_hh[cc], bhz = b_hh[cc + 512], bhn = b_hh[cc + 1024];
#pragma unroll
                for (int rr = 0; rr < 2; rr++) {
                    const float4 xv = rr ? xv1 : xv0;
                    float gir = bir + xv.x*wr.x + xv.y*wr.y + xv.z*wr.z + xv.w*wr.w;
                    float giz = biz + xv.x*wz.x + xv.y*wz.y + xv.z*wz.z + xv.w*wz.w;
                    float gin = bin + xv.x*wnn.x + xv.y*wnn.y + xv.z*wnn.z + xv.w*wnn.w;
                    float ghr = acc[0][i][j][rr * 2 + c] + bhr;
                    float ghz = acc[1][i][j][rr * 2 + c] + bhz;
                    float ghn = acc[2][i][j][rr * 2 + c] + bhn;
                    float rg = sigmoidf_(gir + ghr);
                    float zg = sigmoidf_(giz + ghz);
                    float ng = tanhf(gin + rg * ghn);
                    float hprev = rr ? (c ? hp1.y : hp1.x) : (c ? hp0.y : hp0.x);
                    res[rr][c] = (1.f - zg) * ng + zg * hprev;
                }
            }
            if (hout) {
                *reinterpret_cast<float2*>(&hout[(size_t)r0 * 512 + col])
                    = make_float2(res[0][0], res[0][1]);
                *reinterpret_cast<float2*>(&hout[(size_t)r1 * 512 + col])
                    = make_float2(res[1][0], res[1][1]);
            }
            *reinterpret_cast<__half2*>(&houth[(size_t)r0 * 512 + col])
                = __floats2half2_rn(res[0][0], res[0][1]);
            *reinterpret_cast<__half2*>(&houth[(size_t)r1 * 512 + col])
                = __floats2half2_rn(res[1][0], res[1][1]);
        }
    }
}

// ============================================================
// fc GEMM: hx = concat(h1h,h2h) @ wfch^T + b_fc
// TRIPLE write: hx fp32, hxh fp16, hxRh = relu fp16.
// ============================================================
#define TILE_H (128 * SMSH)
#define GC_SMEM_BYTES (4u * TILE_H * 2u)

__global__ void __launch_bounds__(256, 2)
gemm_fc(const __half* __restrict__ A, const __half* __restrict__ A2,
        const __half* __restrict__ W, const float* __restrict__ bias,
        float* __restrict__ C, __half* __restrict__ Ch, __half* __restrict__ Chr)
{
    extern __shared__ __half smh[];
    const int K = 1024, N = 512;

    const int tid  = threadIdx.x;
    const int warp = tid >> 5;
    const int lane = tid & 31;
    const int gid  = lane >> 2;
    const int tig  = lane & 3;
    const int wm   = warp >> 1;
    const int wn   = warp & 1;
    const int bm   = blockIdx.x * 128;
    const int bn   = blockIdx.y * 128;

    const uint32_t sbase = (uint32_t)__cvta_generic_to_shared(smh);
    const int la_row = ((lane & 8) ? 8 : 0) + (lane & 7);
    const int la_k   = (lane & 16) ? 8 : 0;
    const int lb_n   = ((lane & 16) ? 8 : 0) + (lane & 7);
    const int lb_k   = (lane & 8) ? 8 : 0;

    float acc[2][8][4];
#pragma unroll
    for (int i = 0; i < 2; i++)
#pragma unroll
        for (int j = 0; j < 8; j++)
#pragma unroll
            for (int r = 0; r < 4; r++) acc[i][j][r] = 0.f;

    auto issue_tile = [&](int s, int k0) {
        __half* sAh = smh + s * TILE_H;
        __half* sWh = smh + 2 * TILE_H + s * TILE_H;
#pragma unroll
        for (int it = 0; it < 2; it++) {
            int lin = tid + it * 256;
            int row = lin >> 2, j = lin & 3;
            cp16(&sWh[row * SMSH + j * 8], &W[(size_t)(bn + row) * K + k0 + j * 8]);
            const __half* asrc = (k0 < 512)
                ? &A [(size_t)(bm + row) * 512 + k0 + j * 8]
                : &A2[(size_t)(bm + row) * 512 + (k0 - 512) + j * 8];
            cp16(&sAh[row * SMSH + j * 8], asrc);
        }
        asm volatile("cp.async.commit_group;" ::: "memory");
    };

    const int T = K >> 5;
    issue_tile(0, 0);

    for (int t = 0; t < T; t++) {
        if (t + 1 < T) {
            issue_tile((t + 1) & 1, (t + 1) * 32);
            asm volatile("cp.async.wait_group 1;" ::: "memory");
        } else {
            asm volatile("cp.async.wait_group 0;" ::: "memory");
        }
        __syncthreads();

        const uint32_t stA = sbase + (uint32_t)((t & 1) * TILE_H) * 2u;
        const uint32_t stW = sbase + (uint32_t)((2 + (t & 1)) * TILE_H) * 2u;

#pragma unroll
        for (int kk = 0; kk < 2; kk++) {
            uint32_t afr[2][4];
#pragma unroll
            for (int i = 0; i < 2; i++)
                ldsm_x4(afr[i], stA + (uint32_t)(
                    (wm * 32 + i * 16 + la_row) * SMSH + kk * 16 + la_k) * 2u);
            uint32_t bfr[8][2];
#pragma unroll
            for (int jp = 0; jp < 4; jp++) {
                uint32_t r[4];
                ldsm_x4(r, stW + (uint32_t)(
                    (wn * 64 + jp * 16 + lb_n) * SMSH + kk * 16 + lb_k) * 2u);
                bfr[jp * 2][0]     = r[0]; bfr[jp * 2][1]     = r[1];
                bfr[jp * 2 + 1][0] = r[2]; bfr[jp * 2 + 1][1] = r[3];
            }
#pragma unroll
            for (int i = 0; i < 2; i++)
#pragma unroll
                for (int j = 0; j < 8; j++)
                    mma_f16(acc[i][j], afr[i], bfr[j]);
        }
        __syncthreads();
    }

#pragma unroll
    for (int i = 0; i < 2; i++) {
        int row0 = bm + wm * 32 + i * 16 + gid;
#pragma unroll
        for (int j = 0; j < 8; j++) {
            int col = bn + wn * 64 + j * 8 + tig * 2;
            float b0 = bias[col], b1v = bias[col + 1];
            float v0 = acc[i][j][0] + b0;
            float v1 = acc[i][j][1] + b1v;
            float v2 = acc[i][j][2] + b0;
            float v3 = acc[i][j][3] + b1v;
            *reinterpret_cast<float2*>(&C[(size_t)row0 * N + col]) = make_float2(v0, v1);
            *reinterpret_cast<float2*>(&C[(size_t)(row0 + 8) * N + col]) = make_float2(v2, v3);
            *reinterpret_cast<__half2*>(&Ch[(size_t)row0 * N + col])
                = __floats2half2_rn(v0, v1);
            *reinterpret_cast<__half2*>(&Ch[(size_t)(row0 + 8) * N + col])
                = __floats2half2_rn(v2, v3);
            *reinterpret_cast<__half2*>(&Chr[(size_t)row0 * N + col])
                = __floats2half2_rn(fmaxf(v0, 0.f), fmaxf(v1, 0.f));
            *reinterpret_cast<__half2*>(&Chr[(size_t)(row0 + 8) * N + col])
                = __floats2half2_rn(fmaxf(v2, 0.f), fmaxf(v3, 0.f));
        }
    }
}

// ============================================================
// MLP GEMM fused with w2 contraction (A = relu'd fp16):
// a1 = relu(A @ w1h^T + b1);  dxy += a1 @ w2_slice^T
// ============================================================
__global__ void __launch_bounds__(256, 2)
gemm_mlp(const __half* __restrict__ A, const __half* __restrict__ W,
         const float* __restrict__ b1g, const float* __restrict__ w2,
         float* __restrict__ dxy)
{
    extern __shared__ __half smh[];
    __shared__ float sw2[4][128];
    __shared__ float sdxy[128][4];
    const int K = 512;

    const int tid  = threadIdx.x;
    const int warp = tid >> 5;
    const int lane = tid & 31;
    const int gid  = lane >> 2;
    const int tig  = lane & 3;
    const int wm   = warp >> 1;
    const int wn   = warp & 1;
    const int bm   = blockIdx.x * 128;
    const int bn   = blockIdx.y * 128;

    const uint32_t sbase = (uint32_t)__cvta_generic_to_shared(smh);
    const int la_row = ((lane & 8) ? 8 : 0) + (lane & 7);
    const int la_k   = (lane & 16) ? 8 : 0;
    const int lb_n   = ((lane & 16) ? 8 : 0) + (lane & 7);
    const int lb_k   = (lane & 8) ? 8 : 0;

    for (int i = tid; i < 512; i += 256) {
        sw2[i >> 7][i & 127] = w2[(size_t)(i >> 7) * 2048 + bn + (i & 127)];
        reinterpret_cast<float*>(sdxy)[i] = 0.f;
    }

    float acc[2][8][4];
#pragma unroll
    for (int i = 0; i < 2; i++)
#pragma unroll
        for (int j = 0; j < 8; j++)
#pragma unroll
            for (int r = 0; r < 4; r++) acc[i][j][r] = 0.f;

    auto issue_tile = [&](int s, int k0) {
        __half* sAh = smh + s * TILE_H;
        __half* sWh = smh + 2 * TILE_H + s * TILE_H;
#pragma unroll
        for (int it = 0; it < 2; it++) {
            int lin = tid + it * 256;
            int row = lin >> 2, j = lin & 3;
            cp16(&sWh[row * SMSH + j * 8], &W[(size_t)(bn + row) * K + k0 + j * 8]);
            cp16(&sAh[row * SMSH + j * 8], &A[(size_t)(bm + row) * K + k0 + j * 8]);
        }
        asm volatile("cp.async.commit_group;" ::: "memory");
    };

    const int T = K >> 5;
    issue_tile(0, 0);

    for (int t = 0; t < T; t++) {
        if (t + 1 < T) {
            issue_tile((t + 1) & 1, (t + 1) * 32);
            asm volatile("cp.async.wait_group 1;" ::: "memory");
        } else {
            asm volatile("cp.async.wait_group 0;" ::: "memory");
        }
        __syncthreads();

        const uint32_t stA = sbase + (uint32_t)((t & 1) * TILE_H) * 2u;
        const uint32_t stW = sbase + (uint32_t)((2 + (t & 1)) * TILE_H) * 2u;

#pragma unroll
        for (int kk = 0; kk < 2; kk++) {
            uint32_t afr[2][4];
#pragma unroll
            for (int i = 0; i < 2; i++)
                ldsm_x4(afr[i], stA + (uint32_t)(
                    (wm * 32 + i * 16 + la_row) * SMSH + kk * 16 + la_k) * 2u);
            uint32_t bfr[8][2];
#pragma unroll
            for (int jp = 0; jp < 4; jp++) {
                uint32_t r[4];
                ldsm_x4(r, stW + (uint32_t)(
                    (wn * 64 + jp * 16 + lb_n) * SMSH + kk * 16 + lb_k) * 2u);
                bfr[jp * 2][0]     = r[0]; bfr[jp * 2][1]     = r[1];
                bfr[jp * 2 + 1][0] = r[2]; bfr[jp * 2 + 1][1] = r[3];
            }
#pragma unroll
            for (int i = 0; i < 2; i++)
#pragma unroll
                for (int j = 0; j < 8; j++)
                    mma_f16(acc[i][j], afr[i], bfr[j]);
        }
        __syncthreads();
    }

    // ---- epilogue: contract a1 tile with w2 slice ----
    float p[2][2][4];
#pragma unroll
    for (int i = 0; i < 2; i++)
#pragma unroll
        for (int rr = 0; rr < 2; rr++)
#pragma unroll
            for (int o = 0; o < 4; o++) p[i][rr][o] = 0.f;

#pragma unroll
    for (int i = 0; i < 2; i++)
#pragma unroll
        for (int j = 0; j < 8; j++) {
            const int lc = wn * 64 + j * 8 + tig * 2;
            const float bb0 = b1g[bn + lc], bb1 = b1g[bn + lc + 1];
            const float a00 = fmaxf(acc[i][j][0] + bb0, 0.f);
            const float a01 = fmaxf(acc[i][j][1] + bb1, 0.f);
            const float a10 = fmaxf(acc[i][j][2] + bb0, 0.f);
            const float a11 = fmaxf(acc[i][j][3] + bb1, 0.f);
#pragma unroll
            for (int o = 0; o < 4; o++) {
                const float w0 = sw2[o][lc], w1 = sw2[o][lc + 1];
                p[i][0][o] += a00 * w0 + a01 * w1;
                p[i][1][o] += a10 * w0 + a11 * w1;
            }
        }

#pragma unroll
    for (int i = 0; i < 2; i++)
#pragma unroll
        for (int rr = 0; rr < 2; rr++)
#pragma unroll
            for (int o = 0; o < 4; o++) {
                float v = p[i][rr][o];
                v += __shfl_xor_sync(0xFFFFFFFFu, v, 1);
                v += __shfl_xor_sync(0xFFFFFFFFu, v, 2);
                p[i][rr][o] = v;
            }
    if (tig == 0) {
#pragma unroll
        for (int i = 0; i < 2; i++)
#pragma unroll
            for (int rr = 0; rr < 2; rr++) {
                const int row = wm * 32 + i * 16 + rr * 8 + gid;
#pragma unroll
                for (int o = 0; o < 4; o++)
                    atomicAdd(&sdxy[row][o], p[i][rr][o]);
            }
    }
    __syncthreads();
    for (int i = tid; i < 512; i += 256) {
        const int row = i >> 2, o = i & 3;
        atomicAdd(&dxy[(size_t)(bm + row) * 4 + o], sdxy[row][o]);
    }
}

// ============================================================
// readout: xy += dxy + b2; out[:, step] = xy; dxy = 0
// ============================================================
__global__ void __launch_bounds__(256)
readout_kernel(float* __restrict__ xy, float* __restrict__ dxy,
               const float* __restrict__ b2, float* __restrict__ out, int step)
{
    int i = blockIdx.x * blockDim.x + threadIdx.x;
    if (i < B_) {
        float4 d  = reinterpret_cast<float4*>(dxy)[i];
        float4 xv = reinterpret_cast<float4*>(xy)[i];
        xv.x += d.x + b2[0];
        xv.y += d.y + b2[1];
        xv.z += d.z + b2[2];
        xv.w += d.w + b2[3];
        reinterpret_cast<float4*>(xy)[i] = xv;
        reinterpret_cast<float4*>(out)[(size_t)i * HOR_ + step] = xv;
        reinterpret_cast<float4*>(dxy)[i] = make_float4(0.f, 0.f, 0.f, 0.f);
    }
}

// ============================================================
// Launch
// ============================================================
extern "C" void kernel_launch(void* const* d_in, const int* in_sizes, int n_in,
                              void* d_out, int out_size)
{
    const float* pv   = (const float*)d_in[0];
    const float* ptf  = (const float*)d_in[1];
    const float* w_ih = (const float*)d_in[2];
    const float* w_hh = (const float*)d_in[3];
    const float* b_ih = (const float*)d_in[4];
    const float* b_hh = (const float*)d_in[5];
    const float* w_fc = (const float*)d_in[6];
    const float* b_fc = (const float*)d_in[7];
    const float* w1   = (const float*)d_in[8];
    const float* b1   = (const float*)d_in[9];
    const float* w2   = (const float*)d_in[10];
    const float* b2   = (const float*)d_in[11];
    float* out = (float*)d_out;

    float *h1, *hx, *xy, *dxy;
    __half *h1h, *h2h, *hxh, *hxRh, *ptfh, *whhh, *wfch, *w1h;
    cudaGetSymbolAddress((void**)&h1,   g_h1);
    cudaGetSymbolAddress((void**)&hx,   g_hx);
    cudaGetSymbolAddress((void**)&xy,   g_xy);
    cudaGetSymbolAddress((void**)&dxy,  g_dxy);
    cudaGetSymbolAddress((void**)&h1h,  g_h1h);
    cudaGetSymbolAddress((void**)&h2h,  g_h2h);
    cudaGetSymbolAddress((void**)&hxh,  g_hxh);
    cudaGetSymbolAddress((void**)&hxRh, g_hxRh);
    cudaGetSymbolAddress((void**)&ptfh, g_ptfh);
    cudaGetSymbolAddress((void**)&whhh, g_whhh);
    cudaGetSymbolAddress((void**)&wfch, g_wfch);
    cudaGetSymbolAddress((void**)&w1h,  g_w1h);

    cudaFuncSetAttribute(hh_fused,
        cudaFuncAttributeMaxDynamicSharedMemorySize, HH_SMEM_BYTES);
    cudaFuncSetAttribute(gemm_fc,
        cudaFuncAttributeMaxDynamicSharedMemorySize, GC_SMEM_BYTES);
    cudaFuncSetAttribute(gemm_mlp,
        cudaFuncAttributeMaxDynamicSharedMemorySize, GC_SMEM_BYTES);

    // ---- prep: convert weights + ptf to fp16; zero xy, dxy ----
    cvt_kernel<<<(3 * H_ * H_ / 4 + 255) / 256, 256>>>(w_hh, whhh, 3 * H_ * H_ / 4);
    cvt_kernel<<<(H_ * 2 * H_ / 4 + 255) / 256, 256>>>(w_fc, wfch, H_ * 2 * H_ / 4);
    cvt_kernel<<<(FF_ * H_ / 4 + 255) / 256, 256>>>(w1, w1h, FF_ * H_ / 4);
    cvt_kernel<<<(B_ * H_ / 4 + 255) / 256, 256>>>(ptf, ptfh, B_ * H_ / 4);
    zero_kernel<<<(B_ * OUT_ + 255) / 256, 256>>>(xy, B_ * OUT_);
    zero_kernel<<<(B_ * OUT_ + 255) / 256, 256>>>(dxy, B_ * OUT_);

    const dim3 gridHH(B_ / 128, H_ / 64);      // (128, 8)
    const dim3 gridFC(B_ / 128, H_ / 128);     // (128, 4)
    const dim3 gridM1(B_ / 128, FF_ / 128);    // (128, 16)

    for (int step = 0; step < HOR_; step++) {
        const __half* hxin_h = (step == 0) ? ptfh : hxh;
        const float*  hxin_f = (step == 0) ? ptf  : hx;

        // cell 1 (fused gate): h1 = GRUCell(xy, hx)
        hh_fused<<<gridHH, 256, HH_SMEM_BYTES>>>(
            hxin_h, whhh, hxin_f, xy, OUT_, w_ih, b_ih, b_hh, h1, h1h);

        // cell 2 (fused gate): h2 = GRUCell(pv[:,step], h1)
        hh_fused<<<gridHH, 256, HH_SMEM_BYTES>>>(
            h1h, whhh, h1, pv + step * OUT_, HOR_ * OUT_, w_ih, b_ih, b_hh,
            nullptr, h2h);

        // hx = concat(h1,h2) @ w_fc^T + b_fc  (triple write)
        gemm_fc<<<gridFC, 256, GC_SMEM_BYTES>>>(h1h, h2h, wfch, b_fc,
                                                hx, hxh, hxRh);

        // dxy += (relu(hxRh @ w1^T + b1)) @ w2^T
        gemm_mlp<<<gridM1, 256, GC_SMEM_BYTES>>>(hxRh, w1h, b1, w2, dxy);

        // xy += dxy + b2 ; out[:,step] = xy ; dxy = 0
        readout_kernel<<<B_ / 256, 256>>>(xy, dxy, b2, out, step);
    }
}